// round 2
// baseline (speedup 1.0000x reference)
#include <cuda_runtime.h>
#include <math.h>

// Problem constants
#define BB 128      // batch
#define TT 256      // seq len
#define DD 256      // input dim
#define HH 1024     // hidden dim
#define CC 10       // classes
#define N4 4096     // 4*HH (interleaved gate layout)

// GEMM tile constants
#define BM 64
#define BN 64
#define BK 16
#define NTHREADS 256

// ---------------------------------------------------------------------------
// Scratch (device globals: allocation-free per harness rules)
// ---------------------------------------------------------------------------
__device__ float g_xg[(size_t)TT * BB * N4];   // [T][B][4H] interleaved, 536 MB
__device__ float g_Whr[HH * N4];               // [H][4H] interleaved
__device__ float g_Wxr[DD * N4];               // [D][4H] interleaved
__device__ float g_bbr[N4];                    // interleaved bias
__device__ float g_h[2][BB * HH];              // double-buffered hidden state
__device__ float g_c[BB * HH];                 // cell state (in-place safe)

// ---------------------------------------------------------------------------
// Weight interleave + state init.
// Interleaved column index: n = hp*4 + j, j in {f,i,g,o}.
// ---------------------------------------------------------------------------
__global__ void prep_weights(const float* __restrict__ Wfx, const float* __restrict__ Wix,
                             const float* __restrict__ Wgx, const float* __restrict__ Wox,
                             const float* __restrict__ Wfh, const float* __restrict__ Wih,
                             const float* __restrict__ Wgh, const float* __restrict__ Woh,
                             const float* __restrict__ bf,  const float* __restrict__ bi,
                             const float* __restrict__ bg,  const float* __restrict__ bo)
{
    int idx = blockIdx.x * blockDim.x + threadIdx.x;

    if (idx < DD * HH) {
        int d = idx / HH, hp = idx % HH;
        float* w = g_Wxr + (size_t)d * N4 + hp * 4;
        w[0] = Wfx[idx]; w[1] = Wix[idx]; w[2] = Wgx[idx]; w[3] = Wox[idx];
    }
    if (idx < HH * HH) {
        int h = idx / HH, hp = idx % HH;
        float* w = g_Whr + (size_t)h * N4 + hp * 4;
        w[0] = Wfh[idx]; w[1] = Wih[idx]; w[2] = Wgh[idx]; w[3] = Woh[idx];
    }
    if (idx < HH) {
        g_bbr[idx * 4 + 0] = bf[idx];
        g_bbr[idx * 4 + 1] = bi[idx];
        g_bbr[idx * 4 + 2] = bg[idx];
        g_bbr[idx * 4 + 3] = bo[idx];
    }
    if (idx < BB * HH) {
        g_h[0][idx] = 0.0f;
        g_c[idx]    = 0.0f;
    }
}

// ---------------------------------------------------------------------------
// Precompute xg[r][n] = sum_d x[b][t][d] * Wxr[d][n] + bbr[n]
// Row index r = t*128 + b  (== (t<<7)|b, so b = r&127, t = r>>7).
// Tiled fp32 GEMM: M=32768, K=256, N=4096. Grid: (N/BN=64, M/BM=512).
// ---------------------------------------------------------------------------
__global__ void xg_gemm(const float* __restrict__ x)
{
    __shared__ float As[BM][BK];       // A tile, row-major [m][k]
    __shared__ float Bs[BK][BN];       // B tile, row-major [k][n]

    const int tid = threadIdx.x;
    const int tx = tid & 15;           // 0..15 -> N microtile
    const int ty = tid >> 4;           // 0..15 -> M microtile
    const int n0 = blockIdx.x * BN;
    const int m0 = blockIdx.y * BM;

    // Loader mapping
    const int lm = tid >> 2;           // 0..63  (A row within tile)
    const int lk = (tid & 3) * 4;      // 0,4,8,12 (A k offset, float4)
    const int lkb = tid >> 4;          // 0..15  (B row within tile)
    const int lnb = (tid & 15) * 4;    // B n offset (float4)

    const int gr = m0 + lm;            // global row
    const int b  = gr & (BB - 1);
    const int t  = gr >> 7;
    const float* arow = x + ((size_t)b * TT + t) * DD;

    float acc[4][4] = {};

    for (int k0 = 0; k0 < DD; k0 += BK) {
        *(float4*)&As[lm][lk] = *(const float4*)(arow + k0 + lk);
        *(float4*)&Bs[lkb][lnb] =
            *(const float4*)(g_Wxr + (size_t)(k0 + lkb) * N4 + n0 + lnb);
        __syncthreads();

#pragma unroll
        for (int kk = 0; kk < BK; kk++) {
            float a0 = As[ty * 4 + 0][kk];
            float a1 = As[ty * 4 + 1][kk];
            float a2 = As[ty * 4 + 2][kk];
            float a3 = As[ty * 4 + 3][kk];
            float4 bv = *(float4*)&Bs[kk][tx * 4];
            acc[0][0] += a0 * bv.x; acc[0][1] += a0 * bv.y; acc[0][2] += a0 * bv.z; acc[0][3] += a0 * bv.w;
            acc[1][0] += a1 * bv.x; acc[1][1] += a1 * bv.y; acc[1][2] += a1 * bv.z; acc[1][3] += a1 * bv.w;
            acc[2][0] += a2 * bv.x; acc[2][1] += a2 * bv.y; acc[2][2] += a2 * bv.z; acc[2][3] += a2 * bv.w;
            acc[3][0] += a3 * bv.x; acc[3][1] += a3 * bv.y; acc[3][2] += a3 * bv.z; acc[3][3] += a3 * bv.w;
        }
        __syncthreads();
    }

    const int nb = n0 + tx * 4;
    float4 bias = *(const float4*)(g_bbr + nb);
#pragma unroll
    for (int mi = 0; mi < 4; mi++) {
        int r = m0 + ty * 4 + mi;
        float4 o;
        o.x = acc[mi][0] + bias.x;
        o.y = acc[mi][1] + bias.y;
        o.z = acc[mi][2] + bias.z;
        o.w = acc[mi][3] + bias.w;
        *(float4*)(g_xg + (size_t)r * N4 + nb) = o;
    }
}

__device__ __forceinline__ float sigmoidf_(float v) {
    return 1.0f / (1.0f + expf(-v));
}

// ---------------------------------------------------------------------------
// One LSTM step: gates = xg[t] + h_prev @ Whr, then fused gate epilogue.
// M=128, K=1024, N=4096 interleaved. Grid: (N/BN=64, M/BM=2).
// Each thread's 4 consecutive N columns = the (f,i,g,o) gates of ONE hidden
// unit hp, so the c/h update is thread-local.
// ---------------------------------------------------------------------------
__global__ void lstm_step(int t, int parity)
{
    __shared__ float As[BM][BK];
    __shared__ float Bs[BK][BN];

    const float* __restrict__ hprev = g_h[parity];
    float* __restrict__ hnext = g_h[parity ^ 1];
    const float* __restrict__ xgt = g_xg + (size_t)t * BB * N4;

    const int tid = threadIdx.x;
    const int tx = tid & 15;
    const int ty = tid >> 4;
    const int n0 = blockIdx.x * BN;
    const int m0 = blockIdx.y * BM;

    const int lm = tid >> 2;
    const int lk = (tid & 3) * 4;
    const int lkb = tid >> 4;
    const int lnb = (tid & 15) * 4;

    const float* arow = hprev + (size_t)(m0 + lm) * HH;

    float acc[4][4] = {};

    for (int k0 = 0; k0 < HH; k0 += BK) {
        *(float4*)&As[lm][lk] = *(const float4*)(arow + k0 + lk);
        *(float4*)&Bs[lkb][lnb] =
            *(const float4*)(g_Whr + (size_t)(k0 + lkb) * N4 + n0 + lnb);
        __syncthreads();

#pragma unroll
        for (int kk = 0; kk < BK; kk++) {
            float a0 = As[ty * 4 + 0][kk];
            float a1 = As[ty * 4 + 1][kk];
            float a2 = As[ty * 4 + 2][kk];
            float a3 = As[ty * 4 + 3][kk];
            float4 bv = *(float4*)&Bs[kk][tx * 4];
            acc[0][0] += a0 * bv.x; acc[0][1] += a0 * bv.y; acc[0][2] += a0 * bv.z; acc[0][3] += a0 * bv.w;
            acc[1][0] += a1 * bv.x; acc[1][1] += a1 * bv.y; acc[1][2] += a1 * bv.z; acc[1][3] += a1 * bv.w;
            acc[2][0] += a2 * bv.x; acc[2][1] += a2 * bv.y; acc[2][2] += a2 * bv.z; acc[2][3] += a2 * bv.w;
            acc[3][0] += a3 * bv.x; acc[3][1] += a3 * bv.y; acc[3][2] += a3 * bv.z; acc[3][3] += a3 * bv.w;
        }
        __syncthreads();
    }

    // Fused gate epilogue: columns n0+tx*4 .. +3 are (f,i,g,o) of hidden unit hp.
    const int nb = n0 + tx * 4;
    const int hp = nb >> 2;
#pragma unroll
    for (int mi = 0; mi < 4; mi++) {
        const int m = m0 + ty * 4 + mi;
        float4 xv = *(const float4*)(xgt + (size_t)m * N4 + nb);
        float fg = sigmoidf_(acc[mi][0] + xv.x);
        float ig = sigmoidf_(acc[mi][1] + xv.y);
        float gg = tanhf(acc[mi][2] + xv.z);
        float og = sigmoidf_(acc[mi][3] + xv.w);
        const int hidx = m * HH + hp;
        float cn = gg * ig + g_c[hidx] * fg;
        g_c[hidx] = cn;
        hnext[hidx] = tanhf(cn) * og;
    }
}

// ---------------------------------------------------------------------------
// Final projection: out[b][cc] = h_final[b] . Wph[:,cc] + bp[cc]
// One CTA per batch row, one warp per output class, shfl reduce.
// ---------------------------------------------------------------------------
__global__ void proj_kernel(const float* __restrict__ Wph,
                            const float* __restrict__ bp,
                            float* __restrict__ out)
{
    const int b = blockIdx.x;
    const int w = threadIdx.x >> 5;    // 0..9 (class)
    const int lane = threadIdx.x & 31;
    const float* hr = g_h[0] + (size_t)b * HH;  // T=256 even -> final h in buffer 0

    float s = 0.0f;
    for (int h = lane; h < HH; h += 32)
        s += hr[h] * Wph[(size_t)h * CC + w];
#pragma unroll
    for (int off = 16; off; off >>= 1)
        s += __shfl_xor_sync(0xffffffffu, s, off);
    if (lane == 0)
        out[b * CC + w] = s + bp[w];
}

// ---------------------------------------------------------------------------
// Launch. Graph-capturable: kernel launches only, no allocs, no syncs.
// Input order (metadata): x, Wfx, Wix, Wgx, Wox, Wfh, Wih, Wgh, Woh,
//                         bf, bi, bg, bo, Wph, bp
// ---------------------------------------------------------------------------
extern "C" void kernel_launch(void* const* d_in, const int* in_sizes, int n_in,
                              void* d_out, int out_size)
{
    const float* x   = (const float*)d_in[0];
    const float* Wfx = (const float*)d_in[1];
    const float* Wix = (const float*)d_in[2];
    const float* Wgx = (const float*)d_in[3];
    const float* Wox = (const float*)d_in[4];
    const float* Wfh = (const float*)d_in[5];
    const float* Wih = (const float*)d_in[6];
    const float* Wgh = (const float*)d_in[7];
    const float* Woh = (const float*)d_in[8];
    const float* bf  = (const float*)d_in[9];
    const float* bi  = (const float*)d_in[10];
    const float* bg  = (const float*)d_in[11];
    const float* bo  = (const float*)d_in[12];
    const float* Wph = (const float*)d_in[13];
    const float* bp  = (const float*)d_in[14];
    float* out = (float*)d_out;

    // 1) interleave weights, zero h0/c0  (HH*HH = 1,048,576 threads needed)
    prep_weights<<<(HH * HH + 255) / 256, 256>>>(Wfx, Wix, Wgx, Wox,
                                                 Wfh, Wih, Wgh, Woh,
                                                 bf, bi, bg, bo);

    // 2) precompute all input projections: M=32768, N=4096
    xg_gemm<<<dim3(N4 / BN, (TT * BB) / BM), NTHREADS>>>(x);

    // 3) 256 sequential recurrence steps (double-buffered h)
    for (int t = 0; t < TT; t++)
        lstm_step<<<dim3(N4 / BN, BB / BM), NTHREADS>>>(t, t & 1);

    // 4) final projection
    proj_kernel<<<BB, CC * 32>>>(Wph, bp, out);
}

// round 5
// speedup vs baseline: 2.4261x; 2.4261x over previous
#include <cuda_runtime.h>
#include <cuda_bf16.h>
#include <math.h>
#include <stdint.h>

// Problem constants
#define BB 128      // batch
#define TT 256      // seq len
#define DD 256      // input dim
#define HH 1024     // hidden dim
#define CC 10       // classes
#define N4 4096     // 4*HH

// xg GEMM tile constants (fp32 SIMT precompute, proven in R2)
#define BM 64
#define BN 64
#define BK 16
#define NTHREADS 256

// Step kernel (mma.sync) constants
#define NTHR 256
#define WROW 2064                       // 1024 bf16 = 2048B + 16B pad (conflict-free)
#define S_WHI 0
#define S_WLO (32 * WROW)               // 66048
#define S_ABUF (2 * 32 * WROW)          // 132096
#define ABUF_SZ 32768                   // per buffer: A_hi 16KB + A_lo 16KB
#define STEP_SMEM (S_ABUF + 2 * ABUF_SZ)  // 197632

// ---------------------------------------------------------------------------
// Device globals (allocation-free scratch)
// ---------------------------------------------------------------------------
__device__ float g_xg[(size_t)TT * BB * N4];          // [t*128+b][n=u*4+j] +bias
__device__ float g_Wxr[DD * N4];                      // [D][4H] interleaved fp32
__device__ float g_bbr[N4];                           // bias, n=u*4+j
__device__ __nv_bfloat16 g_Wp_hi[(size_t)N4 * HH];    // Wh^T packed [(u/8)*32+j*8+(u%8)][k]
__device__ __nv_bfloat16 g_Wp_lo[(size_t)N4 * HH];
__device__ __nv_bfloat16 g_hhi[2][BB * HH];           // h bf16 hi (double-buffered)
__device__ __nv_bfloat16 g_hlo[2][BB * HH];           // h bf16 lo
__device__ float g_c[BB * HH];                        // cell state

// ---------------------------------------------------------------------------
// Portable PTX helpers (sm_80-era, legal on compute_103)
// ---------------------------------------------------------------------------
__device__ __forceinline__ uint32_t smem_u32(const void* p) {
    uint32_t a;
    asm("{ .reg .u64 t; cvta.to.shared.u64 t, %1; cvt.u32.u64 %0, t; }" : "=r"(a) : "l"(p));
    return a;
}
__device__ __forceinline__ void cp_async16(uint32_t dst, const void* src) {
    asm volatile("cp.async.cg.shared.global [%0], [%1], 16;" :: "r"(dst), "l"(src));
}
#define CP_COMMIT() asm volatile("cp.async.commit_group;" ::: "memory")
#define CP_WAIT0()  asm volatile("cp.async.wait_group 0;" ::: "memory")
#define CP_WAIT1()  asm volatile("cp.async.wait_group 1;" ::: "memory")

__device__ __forceinline__ void ldmx4(uint32_t* r, uint32_t addr) {
    asm volatile("ldmatrix.sync.aligned.m8n8.x4.shared.b16 {%0,%1,%2,%3}, [%4];"
                 : "=r"(r[0]), "=r"(r[1]), "=r"(r[2]), "=r"(r[3]) : "r"(addr));
}
__device__ __forceinline__ uint32_t lds32(uint32_t addr) {
    uint32_t v;
    asm volatile("ld.shared.u32 %0, [%1];" : "=r"(v) : "r"(addr));
    return v;
}
// D += A(m16k16 bf16) * B(k16n8 bf16), fp32 accum
__device__ __forceinline__ void mma16816(float* d, const uint32_t* a, uint32_t b0, uint32_t b1) {
    asm volatile("mma.sync.aligned.m16n8k16.row.col.f32.bf16.bf16.f32 "
                 "{%0,%1,%2,%3}, {%4,%5,%6,%7}, {%8,%9}, {%0,%1,%2,%3};"
                 : "+f"(d[0]), "+f"(d[1]), "+f"(d[2]), "+f"(d[3])
                 : "r"(a[0]), "r"(a[1]), "r"(a[2]), "r"(a[3]), "r"(b0), "r"(b1));
}

__device__ __forceinline__ float sigf(float x) {
    return 1.0f / (1.0f + __expf(-x));
}

// ---------------------------------------------------------------------------
// Load one A chunk (128 rows x 64 bf16, hi & lo) into swizzled 128B-row tiles.
// 256 threads, 8 cp.async each.
// ---------------------------------------------------------------------------
__device__ __forceinline__ void load_a_chunk(uint32_t dsthi, uint32_t dstlo,
                                             const __nv_bfloat16* __restrict__ srchi,
                                             const __nv_bfloat16* __restrict__ srclo,
                                             int kb, int tid)
{
    const int s  = tid & 7;       // 16B slot within 128B row
    const int r0 = tid >> 3;      // 0..31
    const int ke = kb + s * 8;
#pragma unroll
    for (int p = 0; p < 4; p++) {
        int row = r0 + p * 32;
        uint32_t off = row * 128 + s * 16;
        uint32_t sw  = off ^ ((off >> 3) & 0x70);
        cp_async16(dsthi + sw, srchi + (size_t)row * HH + ke);
        cp_async16(dstlo + sw, srclo + (size_t)row * HH + ke);
    }
}

// ---------------------------------------------------------------------------
// Weight prep:
//  - g_Wxr: [D][4H] interleaved n=u*4+j fp32 (for xg GEMM)
//  - g_Wp_hi/lo: Wh^T packed gate-major n=(u/8)*32+j*8+(u%8), bf16 split
//  - bias interleaved; zero h0 (both splits) and c0.
// ---------------------------------------------------------------------------
__global__ void prep_w(const float* __restrict__ Wfx, const float* __restrict__ Wix,
                       const float* __restrict__ Wgx, const float* __restrict__ Wox,
                       const float* __restrict__ Wfh, const float* __restrict__ Wih,
                       const float* __restrict__ Wgh, const float* __restrict__ Woh,
                       const float* __restrict__ bf,  const float* __restrict__ bi,
                       const float* __restrict__ bg,  const float* __restrict__ bo)
{
    int idx = blockIdx.x * blockDim.x + threadIdx.x;

    if (idx < DD * HH) {
        int d = idx / HH, u = idx % HH;
        float* w = g_Wxr + (size_t)d * N4 + u * 4;
        w[0] = Wfx[idx]; w[1] = Wix[idx]; w[2] = Wgx[idx]; w[3] = Wox[idx];
    }
    if (idx < HH * HH) {
        int k = idx / HH, u = idx % HH;
        float wv[4] = { Wfh[idx], Wih[idx], Wgh[idx], Woh[idx] };
#pragma unroll
        for (int j = 0; j < 4; j++) {
            int n = (u >> 3) * 32 + j * 8 + (u & 7);
            float v = wv[j];
            __nv_bfloat16 hi = __float2bfloat16(v);
            g_Wp_hi[(size_t)n * HH + k] = hi;
            g_Wp_lo[(size_t)n * HH + k] = __float2bfloat16(v - __bfloat162float(hi));
        }
    }
    if (idx < HH) {
        g_bbr[idx * 4 + 0] = bf[idx];
        g_bbr[idx * 4 + 1] = bi[idx];
        g_bbr[idx * 4 + 2] = bg[idx];
        g_bbr[idx * 4 + 3] = bo[idx];
    }
    if (idx < BB * HH) {
        __nv_bfloat16 z = __float2bfloat16(0.0f);
        g_hhi[0][idx] = z; g_hlo[0][idx] = z;
        g_c[idx] = 0.0f;
    }
}

// ---------------------------------------------------------------------------
// xg precompute: xg[r][n] = x[b][t] . Wxr[:,n] + bbr[n], r = t*128+b (fp32 SIMT)
// ---------------------------------------------------------------------------
__global__ void xg_gemm(const float* __restrict__ x)
{
    __shared__ float As[BM][BK];
    __shared__ float Bs[BK][BN];

    const int tid = threadIdx.x;
    const int tx = tid & 15;
    const int ty = tid >> 4;
    const int n0 = blockIdx.x * BN;
    const int m0 = blockIdx.y * BM;

    const int lm = tid >> 2;
    const int lk = (tid & 3) * 4;
    const int lkb = tid >> 4;
    const int lnb = (tid & 15) * 4;

    const int gr = m0 + lm;
    const int b  = gr & (BB - 1);
    const int t  = gr >> 7;
    const float* arow = x + ((size_t)b * TT + t) * DD;

    float acc[4][4] = {};

    for (int k0 = 0; k0 < DD; k0 += BK) {
        *(float4*)&As[lm][lk] = *(const float4*)(arow + k0 + lk);
        *(float4*)&Bs[lkb][lnb] =
            *(const float4*)(g_Wxr + (size_t)(k0 + lkb) * N4 + n0 + lnb);
        __syncthreads();

#pragma unroll
        for (int kk = 0; kk < BK; kk++) {
            float a0 = As[ty * 4 + 0][kk];
            float a1 = As[ty * 4 + 1][kk];
            float a2 = As[ty * 4 + 2][kk];
            float a3 = As[ty * 4 + 3][kk];
            float4 bv = *(float4*)&Bs[kk][tx * 4];
            acc[0][0] += a0 * bv.x; acc[0][1] += a0 * bv.y; acc[0][2] += a0 * bv.z; acc[0][3] += a0 * bv.w;
            acc[1][0] += a1 * bv.x; acc[1][1] += a1 * bv.y; acc[1][2] += a1 * bv.z; acc[1][3] += a1 * bv.w;
            acc[2][0] += a2 * bv.x; acc[2][1] += a2 * bv.y; acc[2][2] += a2 * bv.z; acc[2][3] += a2 * bv.w;
            acc[3][0] += a3 * bv.x; acc[3][1] += a3 * bv.y; acc[3][2] += a3 * bv.z; acc[3][3] += a3 * bv.w;
        }
        __syncthreads();
    }

    const int nb = n0 + tx * 4;
    float4 bias = *(const float4*)(g_bbr + nb);
#pragma unroll
    for (int mi = 0; mi < 4; mi++) {
        int r = m0 + ty * 4 + mi;
        float4 o;
        o.x = acc[mi][0] + bias.x;
        o.y = acc[mi][1] + bias.y;
        o.z = acc[mi][2] + bias.z;
        o.w = acc[mi][3] + bias.w;
        *(float4*)(g_xg + (size_t)r * N4 + nb) = o;
    }
}

// ---------------------------------------------------------------------------
// LSTM step via warp-level tensor-core MMA (bf16 split x3, fp32 accum).
// Grid 128 CTAs x 256 thr. CTA c owns packed cols [c*32, c*32+32) = units
// [c*8, c*8+8). W tile resident in SMEM; A (h) streamed in 16 chunks of 64 K.
// Warp w computes rows [w*16, w*16+16); thread-local (f,i,g,o) quads in the
// epilogue thanks to gate-major packing.
// ---------------------------------------------------------------------------
__global__ void __launch_bounds__(NTHR, 1) lstm_step_mma(int t, int par)
{
    extern __shared__ __align__(1024) char smem[];
    const uint32_t sb = smem_u32(smem);
    const int tid = threadIdx.x;
    const int w = tid >> 5;
    const int lane = tid & 31;
    const int c = blockIdx.x;
    const int n0 = c * 32;

    // ---- W tile (32 x 1024, hi & lo) ----
    {
        const __nv_bfloat16* Whi = g_Wp_hi + (size_t)n0 * HH;
        const __nv_bfloat16* Wlo = g_Wp_lo + (size_t)n0 * HH;
        for (int i = tid; i < 4096; i += NTHR) {
            int n = i >> 7, s = i & 127;
            cp_async16(sb + S_WHI + n * WROW + s * 16, Whi + (size_t)n * HH + s * 8);
            cp_async16(sb + S_WLO + n * WROW + s * 16, Wlo + (size_t)n * HH + s * 8);
        }
    }
    const __nv_bfloat16* Ahi = g_hhi[par];
    const __nv_bfloat16* Alo = g_hlo[par];

    load_a_chunk(sb + S_ABUF, sb + S_ABUF + 16384, Ahi, Alo, 0, tid);
    CP_COMMIT();    // group0 = W + A0
    load_a_chunk(sb + S_ABUF + ABUF_SZ, sb + S_ABUF + ABUF_SZ + 16384, Ahi, Alo, 64, tid);
    CP_COMMIT();    // group1 = A1

    float acc[4][4];
#pragma unroll
    for (int j = 0; j < 4; j++)
#pragma unroll
        for (int q = 0; q < 4; q++) acc[j][q] = 0.0f;

    for (int ch = 0; ch < 16; ch++) {
        if (ch == 15) { CP_WAIT0(); } else { CP_WAIT1(); }
        __syncthreads();

        const uint32_t ahb = sb + S_ABUF + (ch & 1) * ABUF_SZ;
        const uint32_t alb = ahb + 16384;

#pragma unroll
        for (int k16 = 0; k16 < 4; k16++) {
            uint32_t ah[4], al[4];
            uint32_t off = (w * 16 + (lane & 15)) * 128 + (k16 * 2 + (lane >> 4)) * 16;
            uint32_t sw = off ^ ((off >> 3) & 0x70);
            ldmx4(ah, ahb + sw);
            ldmx4(al, alb + sw);

            uint32_t bh[4][2], bl[4][2];
            const int kk = ch * 64 + k16 * 16 + (lane & 3) * 2;   // k element
#pragma unroll
            for (int j = 0; j < 4; j++) {
                uint32_t bo = (uint32_t)(j * 8 + (lane >> 2)) * WROW + kk * 2;
                bh[j][0] = lds32(sb + S_WHI + bo);
                bh[j][1] = lds32(sb + S_WHI + bo + 16);
                bl[j][0] = lds32(sb + S_WLO + bo);
                bl[j][1] = lds32(sb + S_WLO + bo + 16);
            }
#pragma unroll
            for (int j = 0; j < 4; j++) mma16816(acc[j], ah, bh[j][0], bh[j][1]);
#pragma unroll
            for (int j = 0; j < 4; j++) mma16816(acc[j], ah, bl[j][0], bl[j][1]);
#pragma unroll
            for (int j = 0; j < 4; j++) mma16816(acc[j], al, bh[j][0], bh[j][1]);
        }
        __syncthreads();   // all warps done reading this buffer
        if (ch + 2 < 16) {
            uint32_t nb = sb + S_ABUF + (ch & 1) * ABUF_SZ;
            load_a_chunk(nb, nb + 16384, Ahi, Alo, (ch + 2) * 64, tid);
            CP_COMMIT();
        }
    }

    // ---- Epilogue: fused gates, c/h update (thread-local quads) ----
    const int r = lane >> 2;
    const int e2 = (lane & 3) * 2;
    const int rows[2] = { w * 16 + r, w * 16 + r + 8 };
    const int units[2] = { c * 8 + e2, c * 8 + e2 + 1 };
    __nv_bfloat16* hhi_out = g_hhi[par ^ 1];
    __nv_bfloat16* hlo_out = g_hlo[par ^ 1];

#pragma unroll
    for (int rr = 0; rr < 2; rr++) {
#pragma unroll
        for (int uu = 0; uu < 2; uu++) {
            const int q = rr * 2 + uu;          // accumulator fragment index
            const int row = rows[rr];
            const int u = units[uu];
            float4 xv = *(const float4*)(g_xg + ((size_t)t * BB + row) * N4 + u * 4);
            float fg = sigf(acc[0][q] + xv.x);
            float ig = sigf(acc[1][q] + xv.y);
            float gg = tanhf(acc[2][q] + xv.z);
            float og = sigf(acc[3][q] + xv.w);
            const int hidx = row * HH + u;
            float cn = gg * ig + g_c[hidx] * fg;
            g_c[hidx] = cn;
            float hv = tanhf(cn) * og;
            __nv_bfloat16 hb = __float2bfloat16(hv);
            hhi_out[hidx] = hb;
            hlo_out[hidx] = __float2bfloat16(hv - __bfloat162float(hb));
        }
    }
}

// ---------------------------------------------------------------------------
// Final projection: out[b][cc] = h_final[b] . Wph[:,cc] + bp[cc]
// ---------------------------------------------------------------------------
__global__ void proj_kernel(const float* __restrict__ Wph,
                            const float* __restrict__ bp,
                            float* __restrict__ out)
{
    const int b = blockIdx.x;
    const int w = threadIdx.x >> 5;
    const int lane = threadIdx.x & 31;
    const __nv_bfloat16* hhi = g_hhi[0] + (size_t)b * HH;  // T even -> final h in buf 0
    const __nv_bfloat16* hlo = g_hlo[0] + (size_t)b * HH;

    float s = 0.0f;
    for (int h = lane; h < HH; h += 32) {
        float hv = __bfloat162float(hhi[h]) + __bfloat162float(hlo[h]);
        s += hv * Wph[(size_t)h * CC + w];
    }
#pragma unroll
    for (int off = 16; off; off >>= 1)
        s += __shfl_xor_sync(0xffffffffu, s, off);
    if (lane == 0)
        out[b * CC + w] = s + bp[w];
}

// ---------------------------------------------------------------------------
// Launch. Graph-capturable: kernel launches only, no allocs/syncs.
// Inputs: x, Wfx, Wix, Wgx, Wox, Wfh, Wih, Wgh, Woh, bf, bi, bg, bo, Wph, bp
// ---------------------------------------------------------------------------
extern "C" void kernel_launch(void* const* d_in, const int* in_sizes, int n_in,
                              void* d_out, int out_size)
{
    const float* x   = (const float*)d_in[0];
    const float* Wfx = (const float*)d_in[1];
    const float* Wix = (const float*)d_in[2];
    const float* Wgx = (const float*)d_in[3];
    const float* Wox = (const float*)d_in[4];
    const float* Wfh = (const float*)d_in[5];
    const float* Wih = (const float*)d_in[6];
    const float* Wgh = (const float*)d_in[7];
    const float* Woh = (const float*)d_in[8];
    const float* bf  = (const float*)d_in[9];
    const float* bi  = (const float*)d_in[10];
    const float* bg  = (const float*)d_in[11];
    const float* bo  = (const float*)d_in[12];
    const float* Wph = (const float*)d_in[13];
    const float* bp  = (const float*)d_in[14];
    float* out = (float*)d_out;

    cudaFuncSetAttribute(lstm_step_mma, cudaFuncAttributeMaxDynamicSharedMemorySize,
                         STEP_SMEM);

    // 1) weight prep + state init
    prep_w<<<(HH * HH + 255) / 256, 256>>>(Wfx, Wix, Wgx, Wox,
                                           Wfh, Wih, Wgh, Woh,
                                           bf, bi, bg, bo);

    // 2) input projections (fp32 SIMT): M=32768, N=4096, K=256
    xg_gemm<<<dim3(N4 / BN, (TT * BB) / BM), NTHREADS>>>(x);

    // 3) 256 sequential recurrence steps on tensor cores (mma.sync)
    for (int t = 0; t < TT; t++)
        lstm_step_mma<<<BB, NTHR, STEP_SMEM>>>(t, t & 1);

    // 4) final projection
    proj_kernel<<<BB, CC * 32>>>(Wph, bp, out);
}

// round 6
// speedup vs baseline: 2.6861x; 1.1071x over previous
#include <cuda_runtime.h>
#include <cuda_bf16.h>
#include <math.h>
#include <stdint.h>

// Problem constants
#define BB 128      // batch
#define TT 256      // seq len
#define DD 256      // input dim
#define HH 1024     // hidden dim
#define CC 10       // classes
#define N4 4096     // 4*HH
#define NCTA 128    // step-kernel CTAs (one per SM, all resident)

// xg GEMM tile constants (fp32 SIMT precompute, proven)
#define BM 64
#define BN 64
#define BK 16
#define NTHREADS 256

// Step kernel constants
#define NTHR 256
#define WROW 2064                       // 1024 bf16 = 2048B + 16B pad
#define S_WHI 0
#define S_WLO (32 * WROW)               // 66048
#define S_ABUF (2 * 32 * WROW)          // 132096
#define ABUF_SZ 32768                   // per buffer: A_hi 16KB + A_lo 16KB
#define STEP_SMEM (S_ABUF + 2 * ABUF_SZ)  // 197632

// ---------------------------------------------------------------------------
// Device globals (allocation-free scratch)
// ---------------------------------------------------------------------------
__device__ float g_xg[(size_t)TT * BB * N4];          // [t*128+b][n=u*4+j] +bias
__device__ float g_Wxr[DD * N4];                      // [D][4H] interleaved fp32
__device__ float g_bbr[N4];                           // bias, n=u*4+j
__device__ __nv_bfloat16 g_Wp_hi[(size_t)N4 * HH];    // Wh^T packed [(u/8)*32+j*8+(u%8)][k]
__device__ __nv_bfloat16 g_Wp_lo[(size_t)N4 * HH];
__device__ __nv_bfloat16 g_hhi[2][BB * HH];           // h bf16 hi (double-buffered)
__device__ __nv_bfloat16 g_hlo[2][BB * HH];           // h bf16 lo
__device__ unsigned g_barc;                           // grid barrier (monotonic)

// ---------------------------------------------------------------------------
// Portable PTX helpers (sm_80/90-era, legal on compute_103)
// ---------------------------------------------------------------------------
__device__ __forceinline__ uint32_t smem_u32(const void* p) {
    uint32_t a;
    asm("{ .reg .u64 t; cvta.to.shared.u64 t, %1; cvt.u32.u64 %0, t; }" : "=r"(a) : "l"(p));
    return a;
}
__device__ __forceinline__ void cp_async16(uint32_t dst, const void* src) {
    asm volatile("cp.async.cg.shared.global [%0], [%1], 16;" :: "r"(dst), "l"(src));
}
#define CP_COMMIT() asm volatile("cp.async.commit_group;" ::: "memory")
#define CP_WAIT0()  asm volatile("cp.async.wait_group 0;" ::: "memory")
#define CP_WAIT1()  asm volatile("cp.async.wait_group 1;" ::: "memory")

__device__ __forceinline__ void ldmx4(uint32_t* r, uint32_t addr) {
    asm volatile("ldmatrix.sync.aligned.m8n8.x4.shared.b16 {%0,%1,%2,%3}, [%4];"
                 : "=r"(r[0]), "=r"(r[1]), "=r"(r[2]), "=r"(r[3]) : "r"(addr));
}
// D += A(m16k16 bf16) * B(k16n8 bf16), fp32 accum
__device__ __forceinline__ void mma16816(float* d, const uint32_t* a, uint32_t b0, uint32_t b1) {
    asm volatile("mma.sync.aligned.m16n8k16.row.col.f32.bf16.bf16.f32 "
                 "{%0,%1,%2,%3}, {%4,%5,%6,%7}, {%8,%9}, {%0,%1,%2,%3};"
                 : "+f"(d[0]), "+f"(d[1]), "+f"(d[2]), "+f"(d[3])
                 : "r"(a[0]), "r"(a[1]), "r"(a[2]), "r"(a[3]), "r"(b0), "r"(b1));
}

__device__ __forceinline__ float sigf(float x) {
    return 1.0f / (1.0f + __expf(-x));
}

// ---------------------------------------------------------------------------
// Load one A chunk (128 rows x 64 bf16, hi & lo) into swizzled 128B-row tiles.
// ---------------------------------------------------------------------------
__device__ __forceinline__ void load_a_chunk(uint32_t dsthi, uint32_t dstlo,
                                             const __nv_bfloat16* __restrict__ srchi,
                                             const __nv_bfloat16* __restrict__ srclo,
                                             int kb, int tid)
{
    const int s  = tid & 7;       // 16B slot within 128B row
    const int r0 = tid >> 3;      // 0..31
    const int ke = kb + s * 8;
#pragma unroll
    for (int p = 0; p < 4; p++) {
        int row = r0 + p * 32;
        uint32_t off = row * 128 + s * 16;
        uint32_t sw  = off ^ ((off >> 3) & 0x70);
        cp_async16(dsthi + sw, srchi + (size_t)row * HH + ke);
        cp_async16(dstlo + sw, srclo + (size_t)row * HH + ke);
    }
}

// ---------------------------------------------------------------------------
// Weight prep (unchanged numerics from R5) + barrier reset.
// ---------------------------------------------------------------------------
__global__ void prep_w(const float* __restrict__ Wfx, const float* __restrict__ Wix,
                       const float* __restrict__ Wgx, const float* __restrict__ Wox,
                       const float* __restrict__ Wfh, const float* __restrict__ Wih,
                       const float* __restrict__ Wgh, const float* __restrict__ Woh,
                       const float* __restrict__ bf,  const float* __restrict__ bi,
                       const float* __restrict__ bg,  const float* __restrict__ bo)
{
    int idx = blockIdx.x * blockDim.x + threadIdx.x;

    if (idx < DD * HH) {
        int d = idx / HH, u = idx % HH;
        float* w = g_Wxr + (size_t)d * N4 + u * 4;
        w[0] = Wfx[idx]; w[1] = Wix[idx]; w[2] = Wgx[idx]; w[3] = Wox[idx];
    }
    if (idx < HH * HH) {
        int k = idx / HH, u = idx % HH;
        float wv[4] = { Wfh[idx], Wih[idx], Wgh[idx], Woh[idx] };
#pragma unroll
        for (int j = 0; j < 4; j++) {
            int n = (u >> 3) * 32 + j * 8 + (u & 7);
            float v = wv[j];
            __nv_bfloat16 hi = __float2bfloat16(v);
            g_Wp_hi[(size_t)n * HH + k] = hi;
            g_Wp_lo[(size_t)n * HH + k] = __float2bfloat16(v - __bfloat162float(hi));
        }
    }
    if (idx < HH) {
        g_bbr[idx * 4 + 0] = bf[idx];
        g_bbr[idx * 4 + 1] = bi[idx];
        g_bbr[idx * 4 + 2] = bg[idx];
        g_bbr[idx * 4 + 3] = bo[idx];
    }
    if (idx < BB * HH) {
        __nv_bfloat16 z = __float2bfloat16(0.0f);
        g_hhi[0][idx] = z; g_hlo[0][idx] = z;
    }
    if (idx == 0) g_barc = 0;
}

// ---------------------------------------------------------------------------
// xg precompute: xg[r][n] = x[b][t] . Wxr[:,n] + bbr[n], r = t*128+b (fp32 SIMT)
// ---------------------------------------------------------------------------
__global__ void xg_gemm(const float* __restrict__ x)
{
    __shared__ float As[BM][BK];
    __shared__ float Bs[BK][BN];

    const int tid = threadIdx.x;
    const int tx = tid & 15;
    const int ty = tid >> 4;
    const int n0 = blockIdx.x * BN;
    const int m0 = blockIdx.y * BM;

    const int lm = tid >> 2;
    const int lk = (tid & 3) * 4;
    const int lkb = tid >> 4;
    const int lnb = (tid & 15) * 4;

    const int gr = m0 + lm;
    const int b  = gr & (BB - 1);
    const int t  = gr >> 7;
    const float* arow = x + ((size_t)b * TT + t) * DD;

    float acc[4][4] = {};

    for (int k0 = 0; k0 < DD; k0 += BK) {
        *(float4*)&As[lm][lk] = *(const float4*)(arow + k0 + lk);
        *(float4*)&Bs[lkb][lnb] =
            *(const float4*)(g_Wxr + (size_t)(k0 + lkb) * N4 + n0 + lnb);
        __syncthreads();

#pragma unroll
        for (int kk = 0; kk < BK; kk++) {
            float a0 = As[ty * 4 + 0][kk];
            float a1 = As[ty * 4 + 1][kk];
            float a2 = As[ty * 4 + 2][kk];
            float a3 = As[ty * 4 + 3][kk];
            float4 bv = *(float4*)&Bs[kk][tx * 4];
            acc[0][0] += a0 * bv.x; acc[0][1] += a0 * bv.y; acc[0][2] += a0 * bv.z; acc[0][3] += a0 * bv.w;
            acc[1][0] += a1 * bv.x; acc[1][1] += a1 * bv.y; acc[1][2] += a1 * bv.z; acc[1][3] += a1 * bv.w;
            acc[2][0] += a2 * bv.x; acc[2][1] += a2 * bv.y; acc[2][2] += a2 * bv.z; acc[2][3] += a2 * bv.w;
            acc[3][0] += a3 * bv.x; acc[3][1] += a3 * bv.y; acc[3][2] += a3 * bv.z; acc[3][3] += a3 * bv.w;
        }
        __syncthreads();
    }

    const int nb = n0 + tx * 4;
    float4 bias = *(const float4*)(g_bbr + nb);
#pragma unroll
    for (int mi = 0; mi < 4; mi++) {
        int r = m0 + ty * 4 + mi;
        float4 o;
        o.x = acc[mi][0] + bias.x;
        o.y = acc[mi][1] + bias.y;
        o.z = acc[mi][2] + bias.z;
        o.w = acc[mi][3] + bias.w;
        *(float4*)(g_xg + (size_t)r * N4 + nb) = o;
    }
}

// ---------------------------------------------------------------------------
// Persistent LSTM recurrence. 128 CTAs x 256 thr, all resident (1/SM).
// CTA c owns packed cols [c*32, c*32+32) = units [c*8, c*8+8).
// W tile (hi/lo) resident in SMEM for ALL 256 steps; c state in registers.
// Per step: stream h (16 double-buffered chunks), 3-way split MMA, fused
// gate epilogue, grid barrier (monotonic atomic + acquire spin).
// ---------------------------------------------------------------------------
__global__ void __launch_bounds__(NTHR, 1) lstm_persist()
{
    extern __shared__ __align__(1024) char smem[];
    const uint32_t sb = smem_u32(smem);
    const int tid = threadIdx.x;
    const int w = tid >> 5;
    const int lane = tid & 31;
    const int c = blockIdx.x;
    const int n0 = c * 32;

    // ---- one-time W tile load (32 x 1024, hi & lo) ----
    {
        const __nv_bfloat16* Whi = g_Wp_hi + (size_t)n0 * HH;
        const __nv_bfloat16* Wlo = g_Wp_lo + (size_t)n0 * HH;
        for (int i = tid; i < 4096; i += NTHR) {
            int n = i >> 7, s = i & 127;
            cp_async16(sb + S_WHI + n * WROW + s * 16, Whi + (size_t)n * HH + s * 8);
            cp_async16(sb + S_WLO + n * WROW + s * 16, Wlo + (size_t)n * HH + s * 8);
        }
        CP_COMMIT();   // drained by the first CP_WAIT1 below (in-order groups)
    }

    // B-fragment ldmatrix base: lane l supplies row n=l of the 32-row W tile
    const uint32_t wfrag_hi = sb + S_WHI + (uint32_t)lane * WROW;
    const uint32_t wfrag_lo = sb + S_WLO + (uint32_t)lane * WROW;

    // A-fragment swizzled address (fixed per thread except k16)
    const uint32_t a_row_off = (uint32_t)(w * 16 + (lane & 15)) * 128 + (lane >> 4) * 16;

    // epilogue coordinates (fixed): rows w*16 + lane/4 (+8), units c*8+(lane%4)*2 (+1)
    const int row0 = w * 16 + (lane >> 2);
    const int u0 = c * 8 + (lane & 3) * 2;

    float creg[4] = { 0.0f, 0.0f, 0.0f, 0.0f };

    for (int t = 0; t < TT; t++) {
        const int par = t & 1;
        const __nv_bfloat16* Ahi = g_hhi[par];
        const __nv_bfloat16* Alo = g_hlo[par];

        load_a_chunk(sb + S_ABUF, sb + S_ABUF + 16384, Ahi, Alo, 0, tid);
        CP_COMMIT();
        load_a_chunk(sb + S_ABUF + ABUF_SZ, sb + S_ABUF + ABUF_SZ + 16384, Ahi, Alo, 64, tid);
        CP_COMMIT();

        float acc[4][4];
#pragma unroll
        for (int j = 0; j < 4; j++)
#pragma unroll
            for (int q = 0; q < 4; q++) acc[j][q] = 0.0f;

        for (int ch = 0; ch < 16; ch++) {
            if (ch == 15) { CP_WAIT0(); } else { CP_WAIT1(); }
            __syncthreads();

            const uint32_t ahb = sb + S_ABUF + (ch & 1) * ABUF_SZ;
            const uint32_t alb = ahb + 16384;

#pragma unroll
            for (int k16 = 0; k16 < 4; k16++) {
                uint32_t ah[4], al[4];
                uint32_t off = a_row_off + (uint32_t)(k16 * 32);
                uint32_t sw = off ^ ((off >> 3) & 0x70);
                ldmx4(ah, ahb + sw);
                ldmx4(al, alb + sw);

                // W fragments via ldmatrix: reg j = n-block j, two k8 halves
                const uint32_t kb = (uint32_t)(ch * 64 + k16 * 16) * 2;   // bytes
                uint32_t bh0[4], bh1[4], bl0[4], bl1[4];
                ldmx4(bh0, wfrag_hi + kb);
                ldmx4(bh1, wfrag_hi + kb + 16);
                ldmx4(bl0, wfrag_lo + kb);
                ldmx4(bl1, wfrag_lo + kb + 16);

#pragma unroll
                for (int j = 0; j < 4; j++) mma16816(acc[j], ah, bh0[j], bh1[j]);
#pragma unroll
                for (int j = 0; j < 4; j++) mma16816(acc[j], ah, bl0[j], bl1[j]);
#pragma unroll
                for (int j = 0; j < 4; j++) mma16816(acc[j], al, bh0[j], bh1[j]);
            }
            __syncthreads();
            if (ch + 2 < 16) {
                uint32_t nb = sb + S_ABUF + (ch & 1) * ABUF_SZ;
                load_a_chunk(nb, nb + 16384, Ahi, Alo, (ch + 2) * 64, tid);
                CP_COMMIT();
            }
        }

        // ---- epilogue: fused gates, c in registers, write h hi/lo ----
        __nv_bfloat16* hhi_out = g_hhi[par ^ 1];
        __nv_bfloat16* hlo_out = g_hlo[par ^ 1];
#pragma unroll
        for (int rr = 0; rr < 2; rr++) {
#pragma unroll
            for (int uu = 0; uu < 2; uu++) {
                const int q = rr * 2 + uu;
                const int row = row0 + rr * 8;
                const int u = u0 + uu;
                float4 xv = *(const float4*)(g_xg + ((size_t)t * BB + row) * N4 + u * 4);
                float fg = sigf(acc[0][q] + xv.x);
                float ig = sigf(acc[1][q] + xv.y);
                float gg = tanhf(acc[2][q] + xv.z);
                float og = sigf(acc[3][q] + xv.w);
                float cn = gg * ig + creg[q] * fg;
                creg[q] = cn;
                float hv = tanhf(cn) * og;
                __nv_bfloat16 hb = __float2bfloat16(hv);
                const int hidx = row * HH + u;
                hhi_out[hidx] = hb;
                hlo_out[hidx] = __float2bfloat16(hv - __bfloat162float(hb));
            }
        }

        // ---- grid barrier (skip after last step) ----
        if (t < TT - 1) {
            __threadfence();        // h writes visible at gpu scope
            __syncthreads();        // all threads fenced before CTA arrives
            if (tid == 0) {
                atomicAdd(&g_barc, 1u);
                const unsigned target = (unsigned)NCTA * (unsigned)(t + 1);
                unsigned v;
                do {
                    asm volatile("ld.global.acquire.gpu.b32 %0, [%1];"
                                 : "=r"(v) : "l"(&g_barc));
                } while (v < target);
            }
            __syncthreads();
        }
    }
}

// ---------------------------------------------------------------------------
// Final projection: out[b][cc] = h_final[b] . Wph[:,cc] + bp[cc]
// ---------------------------------------------------------------------------
__global__ void proj_kernel(const float* __restrict__ Wph,
                            const float* __restrict__ bp,
                            float* __restrict__ out)
{
    const int b = blockIdx.x;
    const int w = threadIdx.x >> 5;
    const int lane = threadIdx.x & 31;
    const __nv_bfloat16* hhi = g_hhi[0] + (size_t)b * HH;  // T even -> final h in buf 0
    const __nv_bfloat16* hlo = g_hlo[0] + (size_t)b * HH;

    float s = 0.0f;
    for (int h = lane; h < HH; h += 32) {
        float hv = __bfloat162float(hhi[h]) + __bfloat162float(hlo[h]);
        s += hv * Wph[(size_t)h * CC + w];
    }
#pragma unroll
    for (int off = 16; off; off >>= 1)
        s += __shfl_xor_sync(0xffffffffu, s, off);
    if (lane == 0)
        out[b * CC + w] = s + bp[w];
}

// ---------------------------------------------------------------------------
// Launch. Graph-capturable: kernel launches only, no allocs/syncs.
// Inputs: x, Wfx, Wix, Wgx, Wox, Wfh, Wih, Wgh, Woh, bf, bi, bg, bo, Wph, bp
// ---------------------------------------------------------------------------
extern "C" void kernel_launch(void* const* d_in, const int* in_sizes, int n_in,
                              void* d_out, int out_size)
{
    const float* x   = (const float*)d_in[0];
    const float* Wfx = (const float*)d_in[1];
    const float* Wix = (const float*)d_in[2];
    const float* Wgx = (const float*)d_in[3];
    const float* Wox = (const float*)d_in[4];
    const float* Wfh = (const float*)d_in[5];
    const float* Wih = (const float*)d_in[6];
    const float* Wgh = (const float*)d_in[7];
    const float* Woh = (const float*)d_in[8];
    const float* bf  = (const float*)d_in[9];
    const float* bi  = (const float*)d_in[10];
    const float* bg  = (const float*)d_in[11];
    const float* bo  = (const float*)d_in[12];
    const float* Wph = (const float*)d_in[13];
    const float* bp  = (const float*)d_in[14];
    float* out = (float*)d_out;

    cudaFuncSetAttribute(lstm_persist, cudaFuncAttributeMaxDynamicSharedMemorySize,
                         STEP_SMEM);

    // 1) weight prep + state init + barrier reset
    prep_w<<<(HH * HH + 255) / 256, 256>>>(Wfx, Wix, Wgx, Wox,
                                           Wfh, Wih, Wgh, Woh,
                                           bf, bi, bg, bo);

    // 2) input projections (fp32 SIMT): M=32768, N=4096, K=256
    xg_gemm<<<dim3(N4 / BN, (TT * BB) / BM), NTHREADS>>>(x);

    // 3) persistent recurrence: all 256 steps in ONE launch
    lstm_persist<<<NCTA, NTHR, STEP_SMEM>>>();

    // 4) final projection
    proj_kernel<<<BB, CC * 32>>>(Wph, bp, out);
}

// round 7
// speedup vs baseline: 4.3823x; 1.6315x over previous
#include <cuda_runtime.h>
#include <cuda_fp16.h>
#include <math.h>
#include <stdint.h>

// Problem constants
#define BB 128      // batch
#define TT 256      // seq len
#define DD 256      // input dim
#define HH 1024     // hidden dim
#define CC 10       // classes
#define N4 4096     // 4*HH
#define NCTA 128    // persistent CTAs (one per SM)

// xg GEMM tile constants (fp32 SIMT precompute, proven)
#define BM 64
#define BN 64
#define BK 16
#define NTHREADS 256

// Step kernel constants
#define NTHR 256
#define WROW 2064                       // 1024 fp16 = 2048B + 16B pad (conflict-free ldmatrix)
#define S_WT 0                          // W tile: 32 x WROW = 66048
#define S_ABUF (32 * WROW)              // 66048
#define ACH_SZ 16384                    // one A chunk: 128 rows x 64 fp16 (128B rows)
#define STEP_SMEM (S_ABUF + 3 * ACH_SZ) // 115200

// ---------------------------------------------------------------------------
// Device globals (allocation-free scratch)
// ---------------------------------------------------------------------------
__device__ float g_xg[(size_t)TT * BB * N4];        // [t*128+b][n=u*4+j] +bias
__device__ float g_Wxr[DD * N4];                    // [D][4H] interleaved fp32
__device__ float g_bbr[N4];                         // bias, n=u*4+j
__device__ __half g_Wp[(size_t)N4 * HH];            // Wh^T packed [(u/8)*32+j*8+(u%8)][k], fp16
__device__ __half g_h[2][BB * HH];                  // h state fp16 (double-buffered)
__device__ unsigned g_barc;                         // grid barrier (monotonic)

// ---------------------------------------------------------------------------
// Portable PTX helpers (sm_80-era, legal on compute_103)
// ---------------------------------------------------------------------------
__device__ __forceinline__ uint32_t smem_u32(const void* p) {
    uint32_t a;
    asm("{ .reg .u64 t; cvta.to.shared.u64 t, %1; cvt.u32.u64 %0, t; }" : "=r"(a) : "l"(p));
    return a;
}
__device__ __forceinline__ void cp_async16(uint32_t dst, const void* src) {
    asm volatile("cp.async.cg.shared.global [%0], [%1], 16;" :: "r"(dst), "l"(src));
}
#define CP_COMMIT() asm volatile("cp.async.commit_group;" ::: "memory")
#define CP_WAIT0()  asm volatile("cp.async.wait_group 0;" ::: "memory")
#define CP_WAIT1()  asm volatile("cp.async.wait_group 1;" ::: "memory")

__device__ __forceinline__ void ldmx4(uint32_t* r, uint32_t addr) {
    asm volatile("ldmatrix.sync.aligned.m8n8.x4.shared.b16 {%0,%1,%2,%3}, [%4];"
                 : "=r"(r[0]), "=r"(r[1]), "=r"(r[2]), "=r"(r[3]) : "r"(addr));
}
// D += A(m16k16 fp16) * B(k16n8 fp16), fp32 accum
__device__ __forceinline__ void mma16816(float* d, const uint32_t* a, uint32_t b0, uint32_t b1) {
    asm volatile("mma.sync.aligned.m16n8k16.row.col.f32.f16.f16.f32 "
                 "{%0,%1,%2,%3}, {%4,%5,%6,%7}, {%8,%9}, {%0,%1,%2,%3};"
                 : "+f"(d[0]), "+f"(d[1]), "+f"(d[2]), "+f"(d[3])
                 : "r"(a[0]), "r"(a[1]), "r"(a[2]), "r"(a[3]), "r"(b0), "r"(b1));
}

__device__ __forceinline__ float sigf(float x) {
    return 1.0f / (1.0f + __expf(-x));
}

// ---------------------------------------------------------------------------
// Load one A chunk (128 rows x 64 fp16) into a swizzled 128B-row smem tile.
// 256 threads x 4 cp.async(16B) = 16KB.
// ---------------------------------------------------------------------------
__device__ __forceinline__ void load_a_chunk(uint32_t dst,
                                             const __half* __restrict__ src,
                                             int kb, int tid)
{
    const int s  = tid & 7;       // 16B slot within 128B row
    const int r0 = tid >> 3;      // 0..31
    const int ke = kb + s * 8;
#pragma unroll
    for (int p = 0; p < 4; p++) {
        int row = r0 + p * 32;
        uint32_t off = row * 128 + s * 16;
        uint32_t sw  = off ^ ((off >> 3) & 0x70);
        cp_async16(dst + sw, src + (size_t)row * HH + ke);
    }
}

// ---------------------------------------------------------------------------
// Weight prep: Wxr fp32 interleaved (xg GEMM), Wp fp16 packed gate-major
// n = (u/8)*32 + j*8 + (u%8); bias; zero h0; reset barrier.
// ---------------------------------------------------------------------------
__global__ void prep_w(const float* __restrict__ Wfx, const float* __restrict__ Wix,
                       const float* __restrict__ Wgx, const float* __restrict__ Wox,
                       const float* __restrict__ Wfh, const float* __restrict__ Wih,
                       const float* __restrict__ Wgh, const float* __restrict__ Woh,
                       const float* __restrict__ bf,  const float* __restrict__ bi,
                       const float* __restrict__ bg,  const float* __restrict__ bo)
{
    int idx = blockIdx.x * blockDim.x + threadIdx.x;

    if (idx < DD * HH) {
        int d = idx / HH, u = idx % HH;
        float* w = g_Wxr + (size_t)d * N4 + u * 4;
        w[0] = Wfx[idx]; w[1] = Wix[idx]; w[2] = Wgx[idx]; w[3] = Wox[idx];
    }
    if (idx < HH * HH) {
        int k = idx / HH, u = idx % HH;
        float wv[4] = { Wfh[idx], Wih[idx], Wgh[idx], Woh[idx] };
#pragma unroll
        for (int j = 0; j < 4; j++) {
            int n = (u >> 3) * 32 + j * 8 + (u & 7);
            g_Wp[(size_t)n * HH + k] = __float2half(wv[j]);
        }
    }
    if (idx < HH) {
        g_bbr[idx * 4 + 0] = bf[idx];
        g_bbr[idx * 4 + 1] = bi[idx];
        g_bbr[idx * 4 + 2] = bg[idx];
        g_bbr[idx * 4 + 3] = bo[idx];
    }
    if (idx < BB * HH) {
        g_h[0][idx] = __float2half(0.0f);
    }
    if (idx == 0) g_barc = 0;
}

// ---------------------------------------------------------------------------
// xg precompute: xg[r][n] = x[b][t] . Wxr[:,n] + bbr[n], r = t*128+b (fp32 SIMT)
// ---------------------------------------------------------------------------
__global__ void xg_gemm(const float* __restrict__ x)
{
    __shared__ float As[BM][BK];
    __shared__ float Bs[BK][BN];

    const int tid = threadIdx.x;
    const int tx = tid & 15;
    const int ty = tid >> 4;
    const int n0 = blockIdx.x * BN;
    const int m0 = blockIdx.y * BM;

    const int lm = tid >> 2;
    const int lk = (tid & 3) * 4;
    const int lkb = tid >> 4;
    const int lnb = (tid & 15) * 4;

    const int gr = m0 + lm;
    const int b  = gr & (BB - 1);
    const int t  = gr >> 7;
    const float* arow = x + ((size_t)b * TT + t) * DD;

    float acc[4][4] = {};

    for (int k0 = 0; k0 < DD; k0 += BK) {
        *(float4*)&As[lm][lk] = *(const float4*)(arow + k0 + lk);
        *(float4*)&Bs[lkb][lnb] =
            *(const float4*)(g_Wxr + (size_t)(k0 + lkb) * N4 + n0 + lnb);
        __syncthreads();

#pragma unroll
        for (int kk = 0; kk < BK; kk++) {
            float a0 = As[ty * 4 + 0][kk];
            float a1 = As[ty * 4 + 1][kk];
            float a2 = As[ty * 4 + 2][kk];
            float a3 = As[ty * 4 + 3][kk];
            float4 bv = *(float4*)&Bs[kk][tx * 4];
            acc[0][0] += a0 * bv.x; acc[0][1] += a0 * bv.y; acc[0][2] += a0 * bv.z; acc[0][3] += a0 * bv.w;
            acc[1][0] += a1 * bv.x; acc[1][1] += a1 * bv.y; acc[1][2] += a1 * bv.z; acc[1][3] += a1 * bv.w;
            acc[2][0] += a2 * bv.x; acc[2][1] += a2 * bv.y; acc[2][2] += a2 * bv.z; acc[2][3] += a2 * bv.w;
            acc[3][0] += a3 * bv.x; acc[3][1] += a3 * bv.y; acc[3][2] += a3 * bv.z; acc[3][3] += a3 * bv.w;
        }
        __syncthreads();
    }

    const int nb = n0 + tx * 4;
    float4 bias = *(const float4*)(g_bbr + nb);
#pragma unroll
    for (int mi = 0; mi < 4; mi++) {
        int r = m0 + ty * 4 + mi;
        float4 o;
        o.x = acc[mi][0] + bias.x;
        o.y = acc[mi][1] + bias.y;
        o.z = acc[mi][2] + bias.z;
        o.w = acc[mi][3] + bias.w;
        *(float4*)(g_xg + (size_t)r * N4 + nb) = o;
    }
}

// ---------------------------------------------------------------------------
// Persistent LSTM recurrence, fp16 single-MMA.
// 128 CTAs x 256 thr (1/SM). CTA c owns packed cols [c*32,c*32+32) = units
// [c*8,c*8+8). W tile resident in SMEM for all 256 steps; c state in regs.
// 3-stage A pipeline, prefetch distance 2, one __syncthreads per chunk.
// ---------------------------------------------------------------------------
__global__ void __launch_bounds__(NTHR, 1) lstm_persist()
{
    extern __shared__ __align__(1024) char smem[];
    const uint32_t sb = smem_u32(smem);
    const int tid = threadIdx.x;
    const int w = tid >> 5;
    const int lane = tid & 31;
    const int c = blockIdx.x;
    const int n0 = c * 32;

    // ---- one-time W tile load (32 x 1024 fp16) ----
    {
        const __half* Wsrc = g_Wp + (size_t)n0 * HH;
        for (int i = tid; i < 4096; i += NTHR) {
            int n = i >> 7, s = i & 127;
            cp_async16(sb + S_WT + n * WROW + s * 16, Wsrc + (size_t)n * HH + s * 8);
        }
        CP_COMMIT();   // drained by first CP_WAIT1
    }

    // ldmatrix bases
    const uint32_t wfrag = sb + S_WT + (uint32_t)lane * WROW;
    const uint32_t a_row_off = (uint32_t)(w * 16 + (lane & 15)) * 128 + (lane >> 4) * 16;

    // epilogue coordinates (fixed per thread)
    const int row0 = w * 16 + (lane >> 2);
    const int u0 = c * 8 + (lane & 3) * 2;

    float creg[4] = { 0.0f, 0.0f, 0.0f, 0.0f };

    for (int t = 0; t < TT; t++) {
        const int par = t & 1;
        const __half* A = g_h[par];

        // prefetch xg quads for this step's epilogue (DRAM latency hidden)
        float4 xv[4];
#pragma unroll
        for (int rr = 0; rr < 2; rr++)
#pragma unroll
            for (int uu = 0; uu < 2; uu++)
                xv[rr * 2 + uu] = *(const float4*)(
                    g_xg + ((size_t)t * BB + row0 + rr * 8) * N4 + (u0 + uu) * 4);

        // pipeline prologue: chunks 0 and 1
        load_a_chunk(sb + S_ABUF + 0 * ACH_SZ, A, 0, tid);  CP_COMMIT();
        load_a_chunk(sb + S_ABUF + 1 * ACH_SZ, A, 64, tid); CP_COMMIT();

        float acc[4][4];
#pragma unroll
        for (int j = 0; j < 4; j++)
#pragma unroll
            for (int q = 0; q < 4; q++) acc[j][q] = 0.0f;

        for (int ch = 0; ch < 16; ch++) {
            if (ch == 15) { CP_WAIT0(); } else { CP_WAIT1(); }
            __syncthreads();           // chunk ch visible; chunk ch-1 consumed by all

            // issue chunk ch+2 into buffer (ch+2)%3 (freed by chunk ch-1)
            if (ch + 2 < 16) {
                load_a_chunk(sb + S_ABUF + ((ch + 2) % 3) * ACH_SZ, A, (ch + 2) * 64, tid);
                CP_COMMIT();
            }

            const uint32_t ab = sb + S_ABUF + (ch % 3) * ACH_SZ;
#pragma unroll
            for (int k16 = 0; k16 < 4; k16++) {
                uint32_t ah[4];
                uint32_t off = a_row_off + (uint32_t)(k16 * 32);
                uint32_t sw = off ^ ((off >> 3) & 0x70);
                ldmx4(ah, ab + sw);

                const uint32_t kb = (uint32_t)(ch * 64 + k16 * 16) * 2;   // bytes
                uint32_t b0[4], b1[4];
                ldmx4(b0, wfrag + kb);
                ldmx4(b1, wfrag + kb + 16);

#pragma unroll
                for (int j = 0; j < 4; j++) mma16816(acc[j], ah, b0[j], b1[j]);
            }
        }

        // ---- epilogue: fused gates, c in regs, write h fp16 (half2) ----
        __half* hout = g_h[par ^ 1];
#pragma unroll
        for (int rr = 0; rr < 2; rr++) {
            float hv[2];
#pragma unroll
            for (int uu = 0; uu < 2; uu++) {
                const int q = rr * 2 + uu;
                float4 x4 = xv[q];
                float fg = sigf(acc[0][q] + x4.x);
                float ig = sigf(acc[1][q] + x4.y);
                float gg = tanhf(acc[2][q] + x4.z);
                float og = sigf(acc[3][q] + x4.w);
                float cn = gg * ig + creg[q] * fg;
                creg[q] = cn;
                hv[uu] = tanhf(cn) * og;
            }
            const int row = row0 + rr * 8;
            *(__half2*)(hout + (size_t)row * HH + u0) = __floats2half2_rn(hv[0], hv[1]);
        }

        // ---- grid barrier (skip after last step) ----
        if (t < TT - 1) {
            __threadfence();
            __syncthreads();
            if (tid == 0) {
                atomicAdd(&g_barc, 1u);
                const unsigned target = (unsigned)NCTA * (unsigned)(t + 1);
                unsigned v;
                do {
                    asm volatile("ld.global.acquire.gpu.b32 %0, [%1];"
                                 : "=r"(v) : "l"(&g_barc));
                } while (v < target);
            }
            __syncthreads();
        }
    }
}

// ---------------------------------------------------------------------------
// Final projection: out[b][cc] = h_final[b] . Wph[:,cc] + bp[cc]
// ---------------------------------------------------------------------------
__global__ void proj_kernel(const float* __restrict__ Wph,
                            const float* __restrict__ bp,
                            float* __restrict__ out)
{
    const int b = blockIdx.x;
    const int w = threadIdx.x >> 5;
    const int lane = threadIdx.x & 31;
    const __half* hr = g_h[0] + (size_t)b * HH;   // T even -> final h in buf 0

    float s = 0.0f;
    for (int h = lane; h < HH; h += 32)
        s += __half2float(hr[h]) * Wph[(size_t)h * CC + w];
#pragma unroll
    for (int off = 16; off; off >>= 1)
        s += __shfl_xor_sync(0xffffffffu, s, off);
    if (lane == 0)
        out[b * CC + w] = s + bp[w];
}

// ---------------------------------------------------------------------------
// Launch. Graph-capturable: kernel launches only, no allocs/syncs.
// Inputs: x, Wfx, Wix, Wgx, Wox, Wfh, Wih, Wgh, Woh, bf, bi, bg, bo, Wph, bp
// ---------------------------------------------------------------------------
extern "C" void kernel_launch(void* const* d_in, const int* in_sizes, int n_in,
                              void* d_out, int out_size)
{
    const float* x   = (const float*)d_in[0];
    const float* Wfx = (const float*)d_in[1];
    const float* Wix = (const float*)d_in[2];
    const float* Wgx = (const float*)d_in[3];
    const float* Wox = (const float*)d_in[4];
    const float* Wfh = (const float*)d_in[5];
    const float* Wih = (const float*)d_in[6];
    const float* Wgh = (const float*)d_in[7];
    const float* Woh = (const float*)d_in[8];
    const float* bf  = (const float*)d_in[9];
    const float* bi  = (const float*)d_in[10];
    const float* bg  = (const float*)d_in[11];
    const float* bo  = (const float*)d_in[12];
    const float* Wph = (const float*)d_in[13];
    const float* bp  = (const float*)d_in[14];
    float* out = (float*)d_out;

    cudaFuncSetAttribute(lstm_persist, cudaFuncAttributeMaxDynamicSharedMemorySize,
                         STEP_SMEM);

    // 1) weight prep + state init + barrier reset
    prep_w<<<(HH * HH + 255) / 256, 256>>>(Wfx, Wix, Wgx, Wox,
                                           Wfh, Wih, Wgh, Woh,
                                           bf, bi, bg, bo);

    // 2) input projections (fp32 SIMT): M=32768, N=4096, K=256
    xg_gemm<<<dim3(N4 / BN, (TT * BB) / BM), NTHREADS>>>(x);

    // 3) persistent recurrence: all 256 steps in ONE launch (fp16 MMA)
    lstm_persist<<<NCTA, NTHR, STEP_SMEM>>>();

    // 4) final projection
    proj_kernel<<<BB, CC * 32>>>(Wph, bp, out);
}

// round 9
// speedup vs baseline: 7.1377x; 1.6287x over previous
#include <cuda_runtime.h>
#include <cuda_fp16.h>
#include <math.h>
#include <stdint.h>

// Problem constants
#define BB 128      // batch
#define TT 256      // seq len
#define DD 256      // input dim
#define HH 1024     // hidden dim
#define CC 10       // classes
#define N4 4096     // 4*HH
#define NCTA 128    // persistent CTAs (one per SM)

// Step kernel constants
#define NTHR 256
#define WROW 2064                       // 1024 fp16 = 2048B + 16B pad
#define S_WT 0                          // W tile: 32 x WROW = 66048
#define S_ABUF (32 * WROW)              // 66048
#define ACH_SZ 16384                    // one A chunk: 128 rows x 64 fp16
#define STEP_SMEM (S_ABUF + 3 * ACH_SZ) // 115200

// xg MMA kernel constants
#define XG_SMEM 65536                   // 2 buffers x (A 16KB + B 16KB); C staging reuses
#define XCROWH 136                      // C staging row stride in halfs (272B)

// ---------------------------------------------------------------------------
// Device globals (allocation-free scratch)
// ---------------------------------------------------------------------------
__device__ __half g_xg[(size_t)TT * BB * N4];     // [t*128+b][n=u*4+j] fp16, bias included
__device__ __half g_xA[(size_t)TT * BB * DD];     // x rows r=t*128+b, fp16
__device__ __half g_Wxp[(size_t)N4 * DD];         // Wx^T packed [(u/8)*32+j*8+(u%8)][d] fp16
__device__ float  g_bbp[N4];                      // bias packed [n'] fp32
__device__ __half g_Wp[(size_t)N4 * HH];          // Wh^T packed [(u/8)*32+j*8+(u%8)][k] fp16
__device__ __half g_h[2][BB * HH];                // h state fp16 (double-buffered)
__device__ unsigned g_barc;                       // grid barrier (monotonic)

// ---------------------------------------------------------------------------
// Portable PTX helpers (sm_80-era, legal on compute_103)
// ---------------------------------------------------------------------------
__device__ __forceinline__ uint32_t smem_u32(const void* p) {
    uint32_t a;
    asm("{ .reg .u64 t; cvta.to.shared.u64 t, %1; cvt.u32.u64 %0, t; }" : "=r"(a) : "l"(p));
    return a;
}
__device__ __forceinline__ void cp_async16(uint32_t dst, const void* src) {
    asm volatile("cp.async.cg.shared.global [%0], [%1], 16;" :: "r"(dst), "l"(src));
}
#define CP_COMMIT() asm volatile("cp.async.commit_group;" ::: "memory")
#define CP_WAIT0()  asm volatile("cp.async.wait_group 0;" ::: "memory")
#define CP_WAIT1()  asm volatile("cp.async.wait_group 1;" ::: "memory")

__device__ __forceinline__ void ldmx4(uint32_t* r, uint32_t addr) {
    asm volatile("ldmatrix.sync.aligned.m8n8.x4.shared.b16 {%0,%1,%2,%3}, [%4];"
                 : "=r"(r[0]), "=r"(r[1]), "=r"(r[2]), "=r"(r[3]) : "r"(addr));
}
// D += A(m16k16 fp16) * B(k16n8 fp16), fp32 accum
__device__ __forceinline__ void mma16816(float* d, const uint32_t* a, uint32_t b0, uint32_t b1) {
    asm volatile("mma.sync.aligned.m16n8k16.row.col.f32.f16.f16.f32 "
                 "{%0,%1,%2,%3}, {%4,%5,%6,%7}, {%8,%9}, {%0,%1,%2,%3};"
                 : "+f"(d[0]), "+f"(d[1]), "+f"(d[2]), "+f"(d[3])
                 : "r"(a[0]), "r"(a[1]), "r"(a[2]), "r"(a[3]), "r"(b0), "r"(b1));
}

__device__ __forceinline__ float sigf(float x) {
    return 1.0f / (1.0f + __expf(-x));
}

// ---------------------------------------------------------------------------
// Load one 128-row x 64-col fp16 chunk into a swizzled 128B-row smem tile.
// 256 threads x 4 cp.async(16B) = 16KB. row_stride in halfs.
// ---------------------------------------------------------------------------
__device__ __forceinline__ void load_tile128(uint32_t dst,
                                             const __half* __restrict__ src,
                                             int kb, int row_stride, int tid)
{
    const int s  = tid & 7;
    const int r0 = tid >> 3;
    const int ke = kb + s * 8;
#pragma unroll
    for (int p = 0; p < 4; p++) {
        int row = r0 + p * 32;
        uint32_t off = row * 128 + s * 16;
        uint32_t sw  = off ^ ((off >> 3) & 0x70);
        cp_async16(dst + sw, src + (size_t)row * row_stride + ke);
    }
}

// ---------------------------------------------------------------------------
// Weight prep: Wp / Wxp fp16 packed gate-major n'=(u/8)*32+j*8+(u%8);
// packed bias fp32; zero h0; reset barrier.
// ---------------------------------------------------------------------------
__global__ void prep_w(const float* __restrict__ Wfx, const float* __restrict__ Wix,
                       const float* __restrict__ Wgx, const float* __restrict__ Wox,
                       const float* __restrict__ Wfh, const float* __restrict__ Wih,
                       const float* __restrict__ Wgh, const float* __restrict__ Woh,
                       const float* __restrict__ bf,  const float* __restrict__ bi,
                       const float* __restrict__ bg,  const float* __restrict__ bo)
{
    int idx = blockIdx.x * blockDim.x + threadIdx.x;

    if (idx < HH * HH) {
        int k = idx / HH, u = idx % HH;
        float wv[4] = { Wfh[idx], Wih[idx], Wgh[idx], Woh[idx] };
#pragma unroll
        for (int j = 0; j < 4; j++) {
            int n = (u >> 3) * 32 + j * 8 + (u & 7);
            g_Wp[(size_t)n * HH + k] = __float2half(wv[j]);
        }
    }
    if (idx < DD * HH) {
        int d = idx / HH, u = idx % HH;
        float wv[4] = { Wfx[idx], Wix[idx], Wgx[idx], Wox[idx] };
#pragma unroll
        for (int j = 0; j < 4; j++) {
            int n = (u >> 3) * 32 + j * 8 + (u & 7);
            g_Wxp[(size_t)n * DD + d] = __float2half(wv[j]);
        }
    }
    if (idx < HH) {
        int u = idx;
        float bv[4] = { bf[u], bi[u], bg[u], bo[u] };
#pragma unroll
        for (int j = 0; j < 4; j++)
            g_bbp[(u >> 3) * 32 + j * 8 + (u & 7)] = bv[j];
    }
    if (idx < BB * HH) {
        g_h[0][idx] = __float2half(0.0f);
    }
    if (idx == 0) g_barc = 0;
}

// ---------------------------------------------------------------------------
// Convert x[b][t][d] fp32 -> g_xA fp16 rows r = t*128 + b.
// ---------------------------------------------------------------------------
__global__ void prep_x(const float* __restrict__ x)
{
    int idx = blockIdx.x * blockDim.x + threadIdx.x;   // one float4
    int i4 = idx * 4;
    int r = i4 >> 8;
    int d = i4 & (DD - 1);
    int b = r & (BB - 1);
    int t = r >> 7;
    float4 v = *(const float4*)(x + ((size_t)b * TT + t) * DD + d);
    __half2 p0 = __floats2half2_rn(v.x, v.y);
    __half2 p1 = __floats2half2_rn(v.z, v.w);
    uint2 o = { *(uint32_t*)&p0, *(uint32_t*)&p1 };
    *(uint2*)(g_xA + (size_t)r * DD + d) = o;
}

// ---------------------------------------------------------------------------
// xg = xA @ Wxp^T + bias, fp16 tensor-core GEMM.
// M=32768, N=4096 (packed), K=256. CTA tile 128x128, K chunks of 64 (x4).
// Double-buffered cp.async with prefetch distance 1 (race-free: chunk ch+1
// goes to the opposite buffer; end-of-iteration sync protects reuse).
// Output written to g_xg in interleaved layout n = u*4+j via SMEM staging.
// ---------------------------------------------------------------------------
__global__ void __launch_bounds__(256) xg_mma()
{
    extern __shared__ __align__(1024) char smem[];
    const uint32_t sb = smem_u32(smem);
    const int tid = threadIdx.x;
    const int w = tid >> 5;
    const int lane = tid & 31;
    const int N0 = blockIdx.x * 128;    // packed col base
    const int m0 = blockIdx.y * 128;    // row base

    const __half* Asrc = g_xA + (size_t)m0 * DD;
    const __half* Bsrc = g_Wxp + (size_t)N0 * DD;

    // prologue: chunk 0 into buffer 0 (A at +0, B at +16384)
    load_tile128(sb + 0, Asrc, 0, DD, tid);
    load_tile128(sb + 16384, Bsrc, 0, DD, tid);
    CP_COMMIT();

    const uint32_t a_row_off = (uint32_t)(w * 16 + (lane & 15)) * 128 + (lane >> 4) * 16;

    float acc[16][4];
#pragma unroll
    for (int i = 0; i < 16; i++)
#pragma unroll
        for (int q = 0; q < 4; q++) acc[i][q] = 0.0f;

    for (int ch = 0; ch < 4; ch++) {
        // issue chunk ch+1 into the OPPOSITE buffer (freed by end-of-prev-iter sync)
        if (ch + 1 < 4) {
            uint32_t nb = sb + ((ch + 1) & 1) * 32768;
            load_tile128(nb, Asrc, (ch + 1) * 64, DD, tid);
            load_tile128(nb + 16384, Bsrc, (ch + 1) * 64, DD, tid);
            CP_COMMIT();
            CP_WAIT1();          // chunk ch complete (only ch+1 left pending)
        } else {
            CP_WAIT0();          // last chunk complete
        }
        __syncthreads();

        const uint32_t ab = sb + (ch & 1) * 32768;
        const uint32_t bb = ab + 16384;

#pragma unroll
        for (int k16 = 0; k16 < 4; k16++) {
            uint32_t a[4];
            {
                uint32_t off = a_row_off + (uint32_t)(k16 * 32);
                uint32_t sw = off ^ ((off >> 3) & 0x70);
                ldmx4(a, ab + sw);
            }
            uint32_t b0[4][4], b1[4][4];
#pragma unroll
            for (int g = 0; g < 4; g++) {
                uint32_t off0 = (uint32_t)(g * 32 + lane) * 128 + (uint32_t)(k16 * 32);
                uint32_t sw0 = off0 ^ ((off0 >> 3) & 0x70);
                ldmx4(b0[g], bb + sw0);
                uint32_t off1 = off0 + 16;
                uint32_t sw1 = off1 ^ ((off1 >> 3) & 0x70);
                ldmx4(b1[g], bb + sw1);
            }
#pragma unroll
            for (int g = 0; g < 4; g++)
#pragma unroll
                for (int m = 0; m < 4; m++)
                    mma16816(acc[g * 4 + m], a, b0[g][m], b1[g][m]);
        }
        __syncthreads();   // all warps done with buffer ch&1 before it is reloaded
    }

    // ---- epilogue: +bias, fp16, stage in smem, vectorized store ----
    __half* cs = (__half*)smem;          // 128 rows x XCROWH halfs
    const int r0 = w * 16 + (lane >> 2);
    const int e2 = (lane & 3) * 2;
#pragma unroll
    for (int g = 0; g < 4; g++) {
#pragma unroll
        for (int j = 0; j < 4; j++) {
            const int bidx = g * 4 + j;
            float2 bias = *(const float2*)(g_bbp + N0 + g * 32 + j * 8 + e2);
            const int cl0 = (g * 8 + e2) * 4 + j;   // interleaved col in 128-span
            const int cl1 = cl0 + 4;
            cs[r0 * XCROWH + cl0]       = __float2half(acc[bidx][0] + bias.x);
            cs[r0 * XCROWH + cl1]       = __float2half(acc[bidx][1] + bias.y);
            cs[(r0 + 8) * XCROWH + cl0] = __float2half(acc[bidx][2] + bias.x);
            cs[(r0 + 8) * XCROWH + cl1] = __float2half(acc[bidx][3] + bias.y);
        }
    }
    __syncthreads();

    for (int i = tid; i < 128 * 16; i += 256) {
        int row = i >> 4, seg = i & 15;
        uint4 v = *(uint4*)(cs + row * XCROWH + seg * 8);
        *(uint4*)(g_xg + (size_t)(m0 + row) * N4 + N0 + seg * 8) = v;
    }
}

// ---------------------------------------------------------------------------
// Persistent LSTM recurrence, fp16 single-MMA (proven in R7; xg now fp16:
// one 16B load per (row, unit-pair)).
// ---------------------------------------------------------------------------
__global__ void __launch_bounds__(NTHR, 1) lstm_persist()
{
    extern __shared__ __align__(1024) char smem[];
    const uint32_t sb = smem_u32(smem);
    const int tid = threadIdx.x;
    const int w = tid >> 5;
    const int lane = tid & 31;
    const int c = blockIdx.x;
    const int n0 = c * 32;

    // ---- one-time W tile load (32 x 1024 fp16) ----
    {
        const __half* Wsrc = g_Wp + (size_t)n0 * HH;
        for (int i = tid; i < 4096; i += NTHR) {
            int n = i >> 7, s = i & 127;
            cp_async16(sb + S_WT + n * WROW + s * 16, Wsrc + (size_t)n * HH + s * 8);
        }
        CP_COMMIT();   // drained by first CP_WAIT1
    }

    const uint32_t wfrag = sb + S_WT + (uint32_t)lane * WROW;
    const uint32_t a_row_off = (uint32_t)(w * 16 + (lane & 15)) * 128 + (lane >> 4) * 16;

    const int row0 = w * 16 + (lane >> 2);
    const int u0 = c * 8 + (lane & 3) * 2;

    float creg[4] = { 0.0f, 0.0f, 0.0f, 0.0f };

    for (int t = 0; t < TT; t++) {
        const int par = t & 1;
        const __half* A = g_h[par];

        // prefetch this step's xg gate quads (fp16, 16B per row covers 2 units)
        uint4 xq[2];
#pragma unroll
        for (int rr = 0; rr < 2; rr++)
            xq[rr] = *(const uint4*)(
                g_xg + ((size_t)t * BB + row0 + rr * 8) * N4 + u0 * 4);

        load_tile128(sb + S_ABUF + 0 * ACH_SZ, A, 0, HH, tid);  CP_COMMIT();
        load_tile128(sb + S_ABUF + 1 * ACH_SZ, A, 64, HH, tid); CP_COMMIT();

        float acc[4][4];
#pragma unroll
        for (int j = 0; j < 4; j++)
#pragma unroll
            for (int q = 0; q < 4; q++) acc[j][q] = 0.0f;

        for (int ch = 0; ch < 16; ch++) {
            if (ch == 15) { CP_WAIT0(); } else { CP_WAIT1(); }
            __syncthreads();

            if (ch + 2 < 16) {
                load_tile128(sb + S_ABUF + ((ch + 2) % 3) * ACH_SZ, A, (ch + 2) * 64, HH, tid);
                CP_COMMIT();
            }

            const uint32_t ab = sb + S_ABUF + (ch % 3) * ACH_SZ;
#pragma unroll
            for (int k16 = 0; k16 < 4; k16++) {
                uint32_t ah[4];
                uint32_t off = a_row_off + (uint32_t)(k16 * 32);
                uint32_t sw = off ^ ((off >> 3) & 0x70);
                ldmx4(ah, ab + sw);

                const uint32_t kb = (uint32_t)(ch * 64 + k16 * 16) * 2;
                uint32_t b0[4], b1[4];
                ldmx4(b0, wfrag + kb);
                ldmx4(b1, wfrag + kb + 16);

#pragma unroll
                for (int j = 0; j < 4; j++) mma16816(acc[j], ah, b0[j], b1[j]);
            }
        }

        // ---- epilogue: fused gates, c in regs, write h fp16 ----
        __half* hout = g_h[par ^ 1];
#pragma unroll
        for (int rr = 0; rr < 2; rr++) {
            __half2 hfi0 = *(__half2*)&xq[rr].x;   // f,i of unit u0
            __half2 hgo0 = *(__half2*)&xq[rr].y;   // g,o of unit u0
            __half2 hfi1 = *(__half2*)&xq[rr].z;   // f,i of unit u0+1
            __half2 hgo1 = *(__half2*)&xq[rr].w;   // g,o of unit u0+1
            float2 fi0 = __half22float2(hfi0);
            float2 go0 = __half22float2(hgo0);
            float2 fi1 = __half22float2(hfi1);
            float2 go1 = __half22float2(hgo1);

            float hv[2];
            {
                const int q = rr * 2;
                float fg = sigf(acc[0][q] + fi0.x);
                float ig = sigf(acc[1][q] + fi0.y);
                float gg = tanhf(acc[2][q] + go0.x);
                float og = sigf(acc[3][q] + go0.y);
                float cn = gg * ig + creg[q] * fg;
                creg[q] = cn;
                hv[0] = tanhf(cn) * og;
            }
            {
                const int q = rr * 2 + 1;
                float fg = sigf(acc[0][q] + fi1.x);
                float ig = sigf(acc[1][q] + fi1.y);
                float gg = tanhf(acc[2][q] + go1.x);
                float og = sigf(acc[3][q] + go1.y);
                float cn = gg * ig + creg[q] * fg;
                creg[q] = cn;
                hv[1] = tanhf(cn) * og;
            }
            const int row = row0 + rr * 8;
            *(__half2*)(hout + (size_t)row * HH + u0) = __floats2half2_rn(hv[0], hv[1]);
        }

        // ---- grid barrier (skip after last step) ----
        if (t < TT - 1) {
            __threadfence();
            __syncthreads();
            if (tid == 0) {
                atomicAdd(&g_barc, 1u);
                const unsigned target = (unsigned)NCTA * (unsigned)(t + 1);
                unsigned v;
                do {
                    asm volatile("ld.global.acquire.gpu.b32 %0, [%1];"
                                 : "=r"(v) : "l"(&g_barc));
                } while (v < target);
            }
            __syncthreads();
        }
    }
}

// ---------------------------------------------------------------------------
// Final projection: out[b][cc] = h_final[b] . Wph[:,cc] + bp[cc]
// ---------------------------------------------------------------------------
__global__ void proj_kernel(const float* __restrict__ Wph,
                            const float* __restrict__ bp,
                            float* __restrict__ out)
{
    const int b = blockIdx.x;
    const int w = threadIdx.x >> 5;
    const int lane = threadIdx.x & 31;
    const __half* hr = g_h[0] + (size_t)b * HH;   // T even -> final h in buf 0

    float s = 0.0f;
    for (int h = lane; h < HH; h += 32)
        s += __half2float(hr[h]) * Wph[(size_t)h * CC + w];
#pragma unroll
    for (int off = 16; off; off >>= 1)
        s += __shfl_xor_sync(0xffffffffu, s, off);
    if (lane == 0)
        out[b * CC + w] = s + bp[w];
}

// ---------------------------------------------------------------------------
// Launch. Graph-capturable: kernel launches only, no allocs/syncs.
// Inputs: x, Wfx, Wix, Wgx, Wox, Wfh, Wih, Wgh, Woh, bf, bi, bg, bo, Wph, bp
// ---------------------------------------------------------------------------
extern "C" void kernel_launch(void* const* d_in, const int* in_sizes, int n_in,
                              void* d_out, int out_size)
{
    const float* x   = (const float*)d_in[0];
    const float* Wfx = (const float*)d_in[1];
    const float* Wix = (const float*)d_in[2];
    const float* Wgx = (const float*)d_in[3];
    const float* Wox = (const float*)d_in[4];
    const float* Wfh = (const float*)d_in[5];
    const float* Wih = (const float*)d_in[6];
    const float* Wgh = (const float*)d_in[7];
    const float* Woh = (const float*)d_in[8];
    const float* bf  = (const float*)d_in[9];
    const float* bi  = (const float*)d_in[10];
    const float* bg  = (const float*)d_in[11];
    const float* bo  = (const float*)d_in[12];
    const float* Wph = (const float*)d_in[13];
    const float* bp  = (const float*)d_in[14];
    float* out = (float*)d_out;

    cudaFuncSetAttribute(lstm_persist, cudaFuncAttributeMaxDynamicSharedMemorySize,
                         STEP_SMEM);
    cudaFuncSetAttribute(xg_mma, cudaFuncAttributeMaxDynamicSharedMemorySize,
                         XG_SMEM);

    // 1) weight prep + state init + barrier reset
    prep_w<<<(HH * HH + 255) / 256, 256>>>(Wfx, Wix, Wgx, Wox,
                                           Wfh, Wih, Wgh, Woh,
                                           bf, bi, bg, bo);

    // 2) x -> fp16 rows
    prep_x<<<(TT * BB * DD / 4 + 255) / 256, 256>>>(x);

    // 3) input projections on tensor cores: M=32768, N=4096, K=256 fp16
    xg_mma<<<dim3(N4 / 128, (TT * BB) / 128), 256, XG_SMEM>>>();

    // 4) persistent recurrence: all 256 steps in ONE launch (fp16 MMA)
    lstm_persist<<<NCTA, NTHR, STEP_SMEM>>>();

    // 5) final projection
    proj_kernel<<<BB, CC * 32>>>(Wph, bp, out);
}

// round 11
// speedup vs baseline: 7.5483x; 1.0575x over previous
#include <cuda_runtime.h>
#include <cuda_fp16.h>
#include <math.h>
#include <stdint.h>

// Problem constants
#define BB 128      // batch
#define TT 256      // seq len
#define DD 256      // input dim
#define HH 1024     // hidden dim
#define CC 10       // classes
#define N4 4096     // 4*HH
#define NCTA 128    // persistent CTAs (one per SM)

// Step kernel constants
#define NTHR 256
#define WROW 2064                       // 1024 fp16 = 2048B + 16B pad
#define S_WT 0                          // W tile: 64 x WROW = 132096
#define S_ABUF (64 * WROW)              // 132096
#define ACH_SZ 8192                     // one A chunk: 64 rows x 64 fp16
#define STEP_SMEM (S_ABUF + 4 * ACH_SZ) // 164864

// xg MMA kernel constants
#define XG_SMEM 65536
#define XCROWH 136

// ---------------------------------------------------------------------------
// Device globals
// ---------------------------------------------------------------------------
__device__ __half g_xg[(size_t)TT * BB * N4];     // [t*128+b][n=u*4+j] fp16
__device__ __half g_xA[(size_t)TT * BB * DD];     // x rows r=t*128+b fp16
__device__ __half g_Wxp[(size_t)N4 * DD];         // Wx^T packed fp16
__device__ float  g_bbp[N4];                      // bias packed fp32
__device__ __half g_Wp[(size_t)N4 * HH];          // Wh^T packed fp16
__device__ __half g_h[2][BB * HH];                // h state fp16
__device__ unsigned g_barc;                       // grid barrier

// ---------------------------------------------------------------------------
// PTX helpers
// ---------------------------------------------------------------------------
__device__ __forceinline__ uint32_t smem_u32(const void* p) {
    uint32_t a;
    asm("{ .reg .u64 t; cvta.to.shared.u64 t, %1; cvt.u32.u64 %0, t; }" : "=r"(a) : "l"(p));
    return a;
}
__device__ __forceinline__ void cp_async16(uint32_t dst, const void* src) {
    asm volatile("cp.async.cg.shared.global [%0], [%1], 16;" :: "r"(dst), "l"(src));
}
#define CP_COMMIT() asm volatile("cp.async.commit_group;" ::: "memory")
#define CP_WAIT(n)  asm volatile("cp.async.wait_group %0;" :: "n"(n) : "memory")

__device__ __forceinline__ void ldmx4(uint32_t* r, uint32_t addr) {
    asm volatile("ldmatrix.sync.aligned.m8n8.x4.shared.b16 {%0,%1,%2,%3}, [%4];"
                 : "=r"(r[0]), "=r"(r[1]), "=r"(r[2]), "=r"(r[3]) : "r"(addr));
}
__device__ __forceinline__ void mma16816(float* d, const uint32_t* a, uint32_t b0, uint32_t b1) {
    asm volatile("mma.sync.aligned.m16n8k16.row.col.f32.f16.f16.f32 "
                 "{%0,%1,%2,%3}, {%4,%5,%6,%7}, {%8,%9}, {%0,%1,%2,%3};"
                 : "+f"(d[0]), "+f"(d[1]), "+f"(d[2]), "+f"(d[3])
                 : "r"(a[0]), "r"(a[1]), "r"(a[2]), "r"(a[3]), "r"(b0), "r"(b1));
}
__device__ __forceinline__ float sigf(float x) {
    return 1.0f / (1.0f + __expf(-x));
}

// ---------------------------------------------------------------------------
// Coalesced weight pack via 32x32 smem transpose.
// dst (selected DEVICE-SIDE: is_wx ? g_Wxp : g_Wp) [n(u,j)*Kdim + k] = src[k*HH + u]
// Grid (Kdim/32, HH/32), 256 threads.
// NOTE: destination must be resolved in device code — passing a __device__
// array as a host-side kernel argument yields the host shadow address, which
// GB300's ATS silently accepts (writes go to host memory; device array stays 0).
// ---------------------------------------------------------------------------
__global__ void prep_pack(const float* __restrict__ src, int Kdim, int jgate, int is_wx)
{
    __shared__ __half tile[32][33];
    __half* __restrict__ dst = is_wx ? g_Wxp : g_Wp;
    const int k0 = blockIdx.x * 32;
    const int u0 = blockIdx.y * 32;
    const int tid = threadIdx.x;
    const int cx = tid & 31;
    const int ry = tid >> 5;            // 0..7

#pragma unroll
    for (int r = 0; r < 4; r++) {
        int ky = ry + r * 8;
        tile[ky][cx] = __float2half(src[(size_t)(k0 + ky) * HH + u0 + cx]);
    }
    __syncthreads();

#pragma unroll
    for (int r = 0; r < 4; r++) {
        int uy = ry + r * 8;
        int u = u0 + uy;
        int n = (u >> 3) * 32 + jgate * 8 + (u & 7);
        dst[(size_t)n * Kdim + k0 + cx] = tile[cx][uy];
    }
}

// Bias pack + h0 zero + barrier reset.
__global__ void prep_misc(const float* __restrict__ bf, const float* __restrict__ bi,
                          const float* __restrict__ bg, const float* __restrict__ bo)
{
    int idx = blockIdx.x * blockDim.x + threadIdx.x;
    if (idx < HH) {
        int u = idx;
        float bv[4] = { bf[u], bi[u], bg[u], bo[u] };
#pragma unroll
        for (int j = 0; j < 4; j++)
            g_bbp[(u >> 3) * 32 + j * 8 + (u & 7)] = bv[j];
    }
    if (idx < BB * HH)
        g_h[0][idx] = __float2half(0.0f);
    if (idx == 0) g_barc = 0;
}

// x fp32 -> g_xA fp16, rows r = t*128 + b
__global__ void prep_x(const float* __restrict__ x)
{
    int idx = blockIdx.x * blockDim.x + threadIdx.x;
    int i4 = idx * 4;
    int r = i4 >> 8;
    int d = i4 & (DD - 1);
    int b = r & (BB - 1);
    int t = r >> 7;
    float4 v = *(const float4*)(x + ((size_t)b * TT + t) * DD + d);
    __half2 p0 = __floats2half2_rn(v.x, v.y);
    __half2 p1 = __floats2half2_rn(v.z, v.w);
    uint2 o = { *(uint32_t*)&p0, *(uint32_t*)&p1 };
    *(uint2*)(g_xA + (size_t)r * DD + d) = o;
}

// ---------------------------------------------------------------------------
// Load one 128-row x 64-col fp16 chunk (xg_mma A/B tiles), swizzled.
// ---------------------------------------------------------------------------
__device__ __forceinline__ void load_tile128(uint32_t dst,
                                             const __half* __restrict__ src,
                                             int kb, int row_stride, int tid)
{
    const int s  = tid & 7;
    const int r0 = tid >> 3;
    const int ke = kb + s * 8;
#pragma unroll
    for (int p = 0; p < 4; p++) {
        int row = r0 + p * 32;
        uint32_t off = row * 128 + s * 16;
        uint32_t sw  = off ^ ((off >> 3) & 0x70);
        cp_async16(dst + sw, src + (size_t)row * row_stride + ke);
    }
}

// Load one 64-row x 64-col fp16 chunk (recurrence A), swizzled.
__device__ __forceinline__ void load_tile64(uint32_t dst,
                                            const __half* __restrict__ src,
                                            int kb, int tid)
{
    const int s  = tid & 7;
    const int row = tid >> 3;           // 0..31
#pragma unroll
    for (int p = 0; p < 2; p++) {
        int r = row + p * 32;
        uint32_t off = r * 128 + s * 16;
        uint32_t sw  = off ^ ((off >> 3) & 0x70);
        cp_async16(dst + sw, src + (size_t)r * HH + kb + s * 8);
    }
}

// ---------------------------------------------------------------------------
// xg = xA @ Wxp^T + bias (proven R9 kernel)
// ---------------------------------------------------------------------------
__global__ void __launch_bounds__(256) xg_mma()
{
    extern __shared__ __align__(1024) char smem[];
    const uint32_t sb = smem_u32(smem);
    const int tid = threadIdx.x;
    const int w = tid >> 5;
    const int lane = tid & 31;
    const int N0 = blockIdx.x * 128;
    const int m0 = blockIdx.y * 128;

    const __half* Asrc = g_xA + (size_t)m0 * DD;
    const __half* Bsrc = g_Wxp + (size_t)N0 * DD;

    load_tile128(sb + 0, Asrc, 0, DD, tid);
    load_tile128(sb + 16384, Bsrc, 0, DD, tid);
    CP_COMMIT();

    const uint32_t a_row_off = (uint32_t)(w * 16 + (lane & 15)) * 128 + (lane >> 4) * 16;

    float acc[16][4];
#pragma unroll
    for (int i = 0; i < 16; i++)
#pragma unroll
        for (int q = 0; q < 4; q++) acc[i][q] = 0.0f;

    for (int ch = 0; ch < 4; ch++) {
        if (ch + 1 < 4) {
            uint32_t nb = sb + ((ch + 1) & 1) * 32768;
            load_tile128(nb, Asrc, (ch + 1) * 64, DD, tid);
            load_tile128(nb + 16384, Bsrc, (ch + 1) * 64, DD, tid);
            CP_COMMIT();
            CP_WAIT(1);
        } else {
            CP_WAIT(0);
        }
        __syncthreads();

        const uint32_t ab = sb + (ch & 1) * 32768;
        const uint32_t bb = ab + 16384;

#pragma unroll
        for (int k16 = 0; k16 < 4; k16++) {
            uint32_t a[4];
            {
                uint32_t off = a_row_off + (uint32_t)(k16 * 32);
                uint32_t sw = off ^ ((off >> 3) & 0x70);
                ldmx4(a, ab + sw);
            }
            uint32_t b0[4][4], b1[4][4];
#pragma unroll
            for (int g = 0; g < 4; g++) {
                uint32_t off0 = (uint32_t)(g * 32 + lane) * 128 + (uint32_t)(k16 * 32);
                uint32_t sw0 = off0 ^ ((off0 >> 3) & 0x70);
                ldmx4(b0[g], bb + sw0);
                uint32_t off1 = off0 + 16;
                uint32_t sw1 = off1 ^ ((off1 >> 3) & 0x70);
                ldmx4(b1[g], bb + sw1);
            }
#pragma unroll
            for (int g = 0; g < 4; g++)
#pragma unroll
                for (int m = 0; m < 4; m++)
                    mma16816(acc[g * 4 + m], a, b0[g][m], b1[g][m]);
        }
        __syncthreads();
    }

    __half* cs = (__half*)smem;
    const int r0 = w * 16 + (lane >> 2);
    const int e2 = (lane & 3) * 2;
#pragma unroll
    for (int g = 0; g < 4; g++) {
#pragma unroll
        for (int j = 0; j < 4; j++) {
            const int bidx = g * 4 + j;
            float2 bias = *(const float2*)(g_bbp + N0 + g * 32 + j * 8 + e2);
            const int cl0 = (g * 8 + e2) * 4 + j;
            const int cl1 = cl0 + 4;
            cs[r0 * XCROWH + cl0]       = __float2half(acc[bidx][0] + bias.x);
            cs[r0 * XCROWH + cl1]       = __float2half(acc[bidx][1] + bias.y);
            cs[(r0 + 8) * XCROWH + cl0] = __float2half(acc[bidx][2] + bias.x);
            cs[(r0 + 8) * XCROWH + cl1] = __float2half(acc[bidx][3] + bias.y);
        }
    }
    __syncthreads();

    for (int i = tid; i < 128 * 16; i += 256) {
        int row = i >> 4, seg = i & 15;
        uint4 v = *(uint4*)(cs + row * XCROWH + seg * 8);
        *(uint4*)(g_xg + (size_t)(m0 + row) * N4 + N0 + seg * 8) = v;
    }
}

// ---------------------------------------------------------------------------
// Persistent LSTM recurrence, fp16 MMA, CTA tile 64 rows x 64 packed cols.
// Grid 128 = 2 M-groups x 64 N-groups; 8 warps (4m x 2n). W tile resident in
// SMEM; A: 16 chunks of 64x64, 4-buffer pipeline, prefetch distance 3.
// ---------------------------------------------------------------------------
__global__ void __launch_bounds__(NTHR, 1) lstm_persist()
{
    extern __shared__ __align__(1024) char smem[];
    const uint32_t sb = smem_u32(smem);
    const int tid = threadIdx.x;
    const int w = tid >> 5;
    const int lane = tid & 31;
    const int mg = blockIdx.x >> 6;       // 0..1
    const int ng = blockIdx.x & 63;       // 0..63
    const int m_base = mg * 64;
    const int n0 = ng * 64;               // packed col base
    const int mw = w & 3;                 // 0..3
    const int nw = w >> 2;                // 0..1

    // ---- one-time W tile load (64 x 1024 fp16) ----
    {
        const __half* Wsrc = g_Wp + (size_t)n0 * HH;
        for (int i = tid; i < 8192; i += NTHR) {
            int n = i >> 7, s = i & 127;
            cp_async16(sb + S_WT + n * WROW + s * 16, Wsrc + (size_t)n * HH + s * 8);
        }
        CP_COMMIT();
    }

    const uint32_t wfrag = sb + S_WT + (uint32_t)(nw * 32 + lane) * WROW;
    const uint32_t a_row_off = (uint32_t)(mw * 16 + (lane & 15)) * 128 + (lane >> 4) * 16;

    const int row0 = m_base + mw * 16 + (lane >> 2);
    const int u0 = ng * 16 + nw * 8 + (lane & 3) * 2;

    float creg[4] = { 0.0f, 0.0f, 0.0f, 0.0f };

    for (int t = 0; t < TT; t++) {
        const int par = t & 1;
        const __half* A = g_h[par] + (size_t)m_base * HH;

        // prefetch xg gate quads
        uint4 xq[2];
#pragma unroll
        for (int rr = 0; rr < 2; rr++)
            xq[rr] = *(const uint4*)(
                g_xg + ((size_t)t * BB + row0 + rr * 8) * N4 + u0 * 4);

        load_tile64(sb + S_ABUF + 0 * ACH_SZ, A, 0, tid);   CP_COMMIT();
        load_tile64(sb + S_ABUF + 1 * ACH_SZ, A, 64, tid);  CP_COMMIT();
        load_tile64(sb + S_ABUF + 2 * ACH_SZ, A, 128, tid); CP_COMMIT();

        float acc[4][4];
#pragma unroll
        for (int j = 0; j < 4; j++)
#pragma unroll
            for (int q = 0; q < 4; q++) acc[j][q] = 0.0f;

        for (int ch = 0; ch < 16; ch++) {
            if (ch <= 13)       { CP_WAIT(2); }
            else if (ch == 14)  { CP_WAIT(1); }
            else                { CP_WAIT(0); }
            __syncthreads();

            if (ch + 3 < 16) {
                load_tile64(sb + S_ABUF + ((ch + 3) & 3) * ACH_SZ, A, (ch + 3) * 64, tid);
                CP_COMMIT();
            }

            const uint32_t ab = sb + S_ABUF + (ch & 3) * ACH_SZ;
#pragma unroll
            for (int k16 = 0; k16 < 4; k16++) {
                uint32_t ah[4];
                uint32_t off = a_row_off + (uint32_t)(k16 * 32);
                uint32_t sw = off ^ ((off >> 3) & 0x70);
                ldmx4(ah, ab + sw);

                const uint32_t kb = (uint32_t)(ch * 64 + k16 * 16) * 2;
                uint32_t b0[4], b1[4];
                ldmx4(b0, wfrag + kb);
                ldmx4(b1, wfrag + kb + 16);

#pragma unroll
                for (int j = 0; j < 4; j++) mma16816(acc[j], ah, b0[j], b1[j]);
            }
        }

        // ---- epilogue: fused gates, c in regs, write h fp16 ----
        __half* hout = g_h[par ^ 1];
#pragma unroll
        for (int rr = 0; rr < 2; rr++) {
            float2 fi0 = __half22float2(*(__half2*)&xq[rr].x);
            float2 go0 = __half22float2(*(__half2*)&xq[rr].y);
            float2 fi1 = __half22float2(*(__half2*)&xq[rr].z);
            float2 go1 = __half22float2(*(__half2*)&xq[rr].w);

            float hv[2];
            {
                const int q = rr * 2;
                float fg = sigf(acc[0][q] + fi0.x);
                float ig = sigf(acc[1][q] + fi0.y);
                float gg = tanhf(acc[2][q] + go0.x);
                float og = sigf(acc[3][q] + go0.y);
                float cn = gg * ig + creg[q] * fg;
                creg[q] = cn;
                hv[0] = tanhf(cn) * og;
            }
            {
                const int q = rr * 2 + 1;
                float fg = sigf(acc[0][q] + fi1.x);
                float ig = sigf(acc[1][q] + fi1.y);
                float gg = tanhf(acc[2][q] + go1.x);
                float og = sigf(acc[3][q] + go1.y);
                float cn = gg * ig + creg[q] * fg;
                creg[q] = cn;
                hv[1] = tanhf(cn) * og;
            }
            const int row = row0 + rr * 8;
            *(__half2*)(hout + (size_t)row * HH + u0) = __floats2half2_rn(hv[0], hv[1]);
        }

        // ---- grid barrier ----
        if (t < TT - 1) {
            __threadfence();
            __syncthreads();
            if (tid == 0) {
                atomicAdd(&g_barc, 1u);
                const unsigned target = (unsigned)NCTA * (unsigned)(t + 1);
                unsigned v;
                do {
                    asm volatile("ld.global.acquire.gpu.b32 %0, [%1];"
                                 : "=r"(v) : "l"(&g_barc));
                } while (v < target);
            }
            __syncthreads();
        }
    }
}

// ---------------------------------------------------------------------------
// Final projection
// ---------------------------------------------------------------------------
__global__ void proj_kernel(const float* __restrict__ Wph,
                            const float* __restrict__ bp,
                            float* __restrict__ out)
{
    const int b = blockIdx.x;
    const int w = threadIdx.x >> 5;
    const int lane = threadIdx.x & 31;
    const __half* hr = g_h[0] + (size_t)b * HH;

    float s = 0.0f;
    for (int h = lane; h < HH; h += 32)
        s += __half2float(hr[h]) * Wph[(size_t)h * CC + w];
#pragma unroll
    for (int off = 16; off; off >>= 1)
        s += __shfl_xor_sync(0xffffffffu, s, off);
    if (lane == 0)
        out[b * CC + w] = s + bp[w];
}

// ---------------------------------------------------------------------------
// Launch
// ---------------------------------------------------------------------------
extern "C" void kernel_launch(void* const* d_in, const int* in_sizes, int n_in,
                              void* d_out, int out_size)
{
    const float* x   = (const float*)d_in[0];
    const float* Wfx = (const float*)d_in[1];
    const float* Wix = (const float*)d_in[2];
    const float* Wgx = (const float*)d_in[3];
    const float* Wox = (const float*)d_in[4];
    const float* Wfh = (const float*)d_in[5];
    const float* Wih = (const float*)d_in[6];
    const float* Wgh = (const float*)d_in[7];
    const float* Woh = (const float*)d_in[8];
    const float* bf  = (const float*)d_in[9];
    const float* bi  = (const float*)d_in[10];
    const float* bg  = (const float*)d_in[11];
    const float* bo  = (const float*)d_in[12];
    const float* Wph = (const float*)d_in[13];
    const float* bp  = (const float*)d_in[14];
    float* out = (float*)d_out;

    cudaFuncSetAttribute(lstm_persist, cudaFuncAttributeMaxDynamicSharedMemorySize,
                         STEP_SMEM);
    cudaFuncSetAttribute(xg_mma, cudaFuncAttributeMaxDynamicSharedMemorySize,
                         XG_SMEM);

    // 1) weight pack (coalesced transpose; dst selected device-side), bias, h0
    dim3 gh(HH / 32, HH / 32);
    prep_pack<<<gh, 256>>>(Wfh, HH, 0, 0);
    prep_pack<<<gh, 256>>>(Wih, HH, 1, 0);
    prep_pack<<<gh, 256>>>(Wgh, HH, 2, 0);
    prep_pack<<<gh, 256>>>(Woh, HH, 3, 0);
    dim3 gx(DD / 32, HH / 32);
    prep_pack<<<gx, 256>>>(Wfx, DD, 0, 1);
    prep_pack<<<gx, 256>>>(Wix, DD, 1, 1);
    prep_pack<<<gx, 256>>>(Wgx, DD, 2, 1);
    prep_pack<<<gx, 256>>>(Wox, DD, 3, 1);
    prep_misc<<<(BB * HH + 255) / 256, 256>>>(bf, bi, bg, bo);

    // 2) x -> fp16
    prep_x<<<(TT * BB * DD / 4 + 255) / 256, 256>>>(x);

    // 3) input projections (fp16 MMA)
    xg_mma<<<dim3(N4 / 128, (TT * BB) / 128), 256, XG_SMEM>>>();

    // 4) persistent recurrence (fp16 MMA, 64x64 tiles)
    lstm_persist<<<NCTA, NTHR, STEP_SMEM>>>();

    // 5) final projection
    proj_kernel<<<BB, CC * 32>>>(Wph, bp, out);
}

// round 12
// speedup vs baseline: 8.2844x; 1.0975x over previous
#include <cuda_runtime.h>
#include <cuda_fp16.h>
#include <math.h>
#include <stdint.h>

// Problem constants
#define BB 128      // batch
#define TT 256      // seq len
#define DD 256      // input dim
#define HH 1024     // hidden dim
#define CC 10       // classes
#define N4 4096     // 4*HH
#define NCTA 128    // persistent CTAs (one per SM)

// Step kernel constants
#define NTHR 256
#define WROW 2064                       // 1024 fp16 = 2048B + 16B pad
#define S_WT 0                          // W tile: 64 x WROW = 132096
#define S_ABUF (64 * WROW)              // 132096
#define ACH_SZ 16384                    // one A chunk: 64 rows x 128 fp16 (2 subtiles)
#define STEP_SMEM (S_ABUF + 4 * ACH_SZ) // 197632

// xg MMA kernel constants
#define XG_SMEM 65536
#define XCROWH 136

// ---------------------------------------------------------------------------
// Device globals
// ---------------------------------------------------------------------------
__device__ __half g_xg[(size_t)TT * BB * N4];     // [t*128+b][n=u*4+j] fp16
__device__ __half g_xA[(size_t)TT * BB * DD];     // x rows r=t*128+b fp16
__device__ __half g_Wxp[(size_t)N4 * DD];         // Wx^T packed fp16
__device__ float  g_bbp[N4];                      // bias packed fp32
__device__ __half g_Wp[(size_t)N4 * HH];          // Wh^T packed fp16
__device__ __half g_h[2][BB * HH];                // h state fp16
__device__ unsigned g_barc[2];                    // per-mg-group grid barriers

// ---------------------------------------------------------------------------
// PTX helpers
// ---------------------------------------------------------------------------
__device__ __forceinline__ uint32_t smem_u32(const void* p) {
    uint32_t a;
    asm("{ .reg .u64 t; cvta.to.shared.u64 t, %1; cvt.u32.u64 %0, t; }" : "=r"(a) : "l"(p));
    return a;
}
__device__ __forceinline__ void cp_async16(uint32_t dst, const void* src) {
    asm volatile("cp.async.cg.shared.global [%0], [%1], 16;" :: "r"(dst), "l"(src));
}
#define CP_COMMIT() asm volatile("cp.async.commit_group;" ::: "memory")
#define CP_WAIT(n)  asm volatile("cp.async.wait_group %0;" :: "n"(n) : "memory")

__device__ __forceinline__ void ldmx4(uint32_t* r, uint32_t addr) {
    asm volatile("ldmatrix.sync.aligned.m8n8.x4.shared.b16 {%0,%1,%2,%3}, [%4];"
                 : "=r"(r[0]), "=r"(r[1]), "=r"(r[2]), "=r"(r[3]) : "r"(addr));
}
__device__ __forceinline__ void mma16816(float* d, const uint32_t* a, uint32_t b0, uint32_t b1) {
    asm volatile("mma.sync.aligned.m16n8k16.row.col.f32.f16.f16.f32 "
                 "{%0,%1,%2,%3}, {%4,%5,%6,%7}, {%8,%9}, {%0,%1,%2,%3};"
                 : "+f"(d[0]), "+f"(d[1]), "+f"(d[2]), "+f"(d[3])
                 : "r"(a[0]), "r"(a[1]), "r"(a[2]), "r"(a[3]), "r"(b0), "r"(b1));
}
__device__ __forceinline__ float sigf(float x) {
    return 1.0f / (1.0f + __expf(-x));
}

// ---------------------------------------------------------------------------
// Coalesced weight pack via 32x32 smem transpose. dst selected DEVICE-SIDE
// (GB300 ATS silently accepts host shadow addresses of __device__ arrays).
// ---------------------------------------------------------------------------
__global__ void prep_pack(const float* __restrict__ src, int Kdim, int jgate, int is_wx)
{
    __shared__ __half tile[32][33];
    __half* __restrict__ dst = is_wx ? g_Wxp : g_Wp;
    const int k0 = blockIdx.x * 32;
    const int u0 = blockIdx.y * 32;
    const int tid = threadIdx.x;
    const int cx = tid & 31;
    const int ry = tid >> 5;

#pragma unroll
    for (int r = 0; r < 4; r++) {
        int ky = ry + r * 8;
        tile[ky][cx] = __float2half(src[(size_t)(k0 + ky) * HH + u0 + cx]);
    }
    __syncthreads();

#pragma unroll
    for (int r = 0; r < 4; r++) {
        int uy = ry + r * 8;
        int u = u0 + uy;
        int n = (u >> 3) * 32 + jgate * 8 + (u & 7);
        dst[(size_t)n * Kdim + k0 + cx] = tile[cx][uy];
    }
}

// Bias pack + h0 zero + barrier reset.
__global__ void prep_misc(const float* __restrict__ bf, const float* __restrict__ bi,
                          const float* __restrict__ bg, const float* __restrict__ bo)
{
    int idx = blockIdx.x * blockDim.x + threadIdx.x;
    if (idx < HH) {
        int u = idx;
        float bv[4] = { bf[u], bi[u], bg[u], bo[u] };
#pragma unroll
        for (int j = 0; j < 4; j++)
            g_bbp[(u >> 3) * 32 + j * 8 + (u & 7)] = bv[j];
    }
    if (idx < BB * HH)
        g_h[0][idx] = __float2half(0.0f);
    if (idx < 2) g_barc[idx] = 0;
}

// x fp32 -> g_xA fp16, rows r = t*128 + b
__global__ void prep_x(const float* __restrict__ x)
{
    int idx = blockIdx.x * blockDim.x + threadIdx.x;
    int i4 = idx * 4;
    int r = i4 >> 8;
    int d = i4 & (DD - 1);
    int b = r & (BB - 1);
    int t = r >> 7;
    float4 v = *(const float4*)(x + ((size_t)b * TT + t) * DD + d);
    __half2 p0 = __floats2half2_rn(v.x, v.y);
    __half2 p1 = __floats2half2_rn(v.z, v.w);
    uint2 o = { *(uint32_t*)&p0, *(uint32_t*)&p1 };
    *(uint2*)(g_xA + (size_t)r * DD + d) = o;
}

// ---------------------------------------------------------------------------
// Load one 128-row x 64-col fp16 chunk (xg_mma tiles), swizzled.
// ---------------------------------------------------------------------------
__device__ __forceinline__ void load_tile128(uint32_t dst,
                                             const __half* __restrict__ src,
                                             int kb, int row_stride, int tid)
{
    const int s  = tid & 7;
    const int r0 = tid >> 3;
    const int ke = kb + s * 8;
#pragma unroll
    for (int p = 0; p < 4; p++) {
        int row = r0 + p * 32;
        uint32_t off = row * 128 + s * 16;
        uint32_t sw  = off ^ ((off >> 3) & 0x70);
        cp_async16(dst + sw, src + (size_t)row * row_stride + ke);
    }
}

// Load one 64-row x 64-col fp16 subtile (recurrence A), swizzled.
__device__ __forceinline__ void load_tile64(uint32_t dst,
                                            const __half* __restrict__ src,
                                            int kb, int tid)
{
    const int s  = tid & 7;
    const int row = tid >> 3;
#pragma unroll
    for (int p = 0; p < 2; p++) {
        int r = row + p * 32;
        uint32_t off = r * 128 + s * 16;
        uint32_t sw  = off ^ ((off >> 3) & 0x70);
        cp_async16(dst + sw, src + (size_t)r * HH + kb + s * 8);
    }
}

// ---------------------------------------------------------------------------
// xg = xA @ Wxp^T + bias (proven kernel, unchanged)
// ---------------------------------------------------------------------------
__global__ void __launch_bounds__(256) xg_mma()
{
    extern __shared__ __align__(1024) char smem[];
    const uint32_t sb = smem_u32(smem);
    const int tid = threadIdx.x;
    const int w = tid >> 5;
    const int lane = tid & 31;
    const int N0 = blockIdx.x * 128;
    const int m0 = blockIdx.y * 128;

    const __half* Asrc = g_xA + (size_t)m0 * DD;
    const __half* Bsrc = g_Wxp + (size_t)N0 * DD;

    load_tile128(sb + 0, Asrc, 0, DD, tid);
    load_tile128(sb + 16384, Bsrc, 0, DD, tid);
    CP_COMMIT();

    const uint32_t a_row_off = (uint32_t)(w * 16 + (lane & 15)) * 128 + (lane >> 4) * 16;

    float acc[16][4];
#pragma unroll
    for (int i = 0; i < 16; i++)
#pragma unroll
        for (int q = 0; q < 4; q++) acc[i][q] = 0.0f;

    for (int ch = 0; ch < 4; ch++) {
        if (ch + 1 < 4) {
            uint32_t nb = sb + ((ch + 1) & 1) * 32768;
            load_tile128(nb, Asrc, (ch + 1) * 64, DD, tid);
            load_tile128(nb + 16384, Bsrc, (ch + 1) * 64, DD, tid);
            CP_COMMIT();
            CP_WAIT(1);
        } else {
            CP_WAIT(0);
        }
        __syncthreads();

        const uint32_t ab = sb + (ch & 1) * 32768;
        const uint32_t bb = ab + 16384;

#pragma unroll
        for (int k16 = 0; k16 < 4; k16++) {
            uint32_t a[4];
            {
                uint32_t off = a_row_off + (uint32_t)(k16 * 32);
                uint32_t sw = off ^ ((off >> 3) & 0x70);
                ldmx4(a, ab + sw);
            }
            uint32_t b0[4][4], b1[4][4];
#pragma unroll
            for (int g = 0; g < 4; g++) {
                uint32_t off0 = (uint32_t)(g * 32 + lane) * 128 + (uint32_t)(k16 * 32);
                uint32_t sw0 = off0 ^ ((off0 >> 3) & 0x70);
                ldmx4(b0[g], bb + sw0);
                uint32_t off1 = off0 + 16;
                uint32_t sw1 = off1 ^ ((off1 >> 3) & 0x70);
                ldmx4(b1[g], bb + sw1);
            }
#pragma unroll
            for (int g = 0; g < 4; g++)
#pragma unroll
                for (int m = 0; m < 4; m++)
                    mma16816(acc[g * 4 + m], a, b0[g][m], b1[g][m]);
        }
        __syncthreads();
    }

    __half* cs = (__half*)smem;
    const int r0 = w * 16 + (lane >> 2);
    const int e2 = (lane & 3) * 2;
#pragma unroll
    for (int g = 0; g < 4; g++) {
#pragma unroll
        for (int j = 0; j < 4; j++) {
            const int bidx = g * 4 + j;
            float2 bias = *(const float2*)(g_bbp + N0 + g * 32 + j * 8 + e2);
            const int cl0 = (g * 8 + e2) * 4 + j;
            const int cl1 = cl0 + 4;
            cs[r0 * XCROWH + cl0]       = __float2half(acc[bidx][0] + bias.x);
            cs[r0 * XCROWH + cl1]       = __float2half(acc[bidx][1] + bias.y);
            cs[(r0 + 8) * XCROWH + cl0] = __float2half(acc[bidx][2] + bias.x);
            cs[(r0 + 8) * XCROWH + cl1] = __float2half(acc[bidx][3] + bias.y);
        }
    }
    __syncthreads();

    for (int i = tid; i < 128 * 16; i += 256) {
        int row = i >> 4, seg = i & 15;
        uint4 v = *(uint4*)(cs + row * XCROWH + seg * 8);
        *(uint4*)(g_xg + (size_t)(m0 + row) * N4 + N0 + seg * 8) = v;
    }
}

// ---------------------------------------------------------------------------
// Persistent LSTM recurrence, fp16 MMA, CTA tile 64 rows x 64 packed cols.
// 8 chunks of 128 K per step (each = 2 swizzled 64-col subtiles), 4-buffer
// pipeline distance 3. Two INDEPENDENT 64-CTA barriers (batch halves never
// interact). Fence by elected thread only (CG grid.sync pattern). xq gate
// quads prefetched one step ahead, hidden behind the barrier spin.
// ---------------------------------------------------------------------------
__global__ void __launch_bounds__(NTHR, 1) lstm_persist()
{
    extern __shared__ __align__(1024) char smem[];
    const uint32_t sb = smem_u32(smem);
    const int tid = threadIdx.x;
    const int w = tid >> 5;
    const int lane = tid & 31;
    const int mg = blockIdx.x >> 6;       // 0..1 (independent batch half)
    const int ng = blockIdx.x & 63;       // 0..63
    const int m_base = mg * 64;
    const int n0 = ng * 64;
    const int mw = w & 3;
    const int nw = w >> 2;

    // ---- one-time W tile load (64 x 1024 fp16) ----
    {
        const __half* Wsrc = g_Wp + (size_t)n0 * HH;
        for (int i = tid; i < 8192; i += NTHR) {
            int n = i >> 7, s = i & 127;
            cp_async16(sb + S_WT + n * WROW + s * 16, Wsrc + (size_t)n * HH + s * 8);
        }
        CP_COMMIT();
    }

    const uint32_t wfrag = sb + S_WT + (uint32_t)(nw * 32 + lane) * WROW;
    const uint32_t a_row_off = (uint32_t)(mw * 16 + (lane & 15)) * 128 + (lane >> 4) * 16;

    const int row0 = m_base + mw * 16 + (lane >> 2);
    const int u0 = ng * 16 + nw * 8 + (lane & 3) * 2;
    const __half* xg_base0 = g_xg + (size_t)row0 * N4 + u0 * 4;
    const __half* xg_base1 = g_xg + (size_t)(row0 + 8) * N4 + u0 * 4;

    float creg[4] = { 0.0f, 0.0f, 0.0f, 0.0f };

    // xq for t=0
    uint4 xq[2];
    xq[0] = *(const uint4*)(xg_base0);
    xq[1] = *(const uint4*)(xg_base1);

    unsigned* const barp = &g_barc[mg];

    for (int t = 0; t < TT; t++) {
        const int par = t & 1;
        const __half* A = g_h[par] + (size_t)m_base * HH;

        // pipeline prologue: chunks 0..2 (each 128 K = 2 subtiles)
#pragma unroll
        for (int pc = 0; pc < 3; pc++) {
            uint32_t db = sb + S_ABUF + pc * ACH_SZ;
            load_tile64(db, A, pc * 128, tid);
            load_tile64(db + 8192, A, pc * 128 + 64, tid);
            CP_COMMIT();
        }

        float acc[4][4];
#pragma unroll
        for (int j = 0; j < 4; j++)
#pragma unroll
            for (int q = 0; q < 4; q++) acc[j][q] = 0.0f;

        for (int ch = 0; ch < 8; ch++) {
            if (ch <= 5)      { CP_WAIT(2); }
            else if (ch == 6) { CP_WAIT(1); }
            else              { CP_WAIT(0); }
            __syncthreads();

            if (ch + 3 < 8) {
                uint32_t db = sb + S_ABUF + ((ch + 3) & 3) * ACH_SZ;
                load_tile64(db, A, (ch + 3) * 128, tid);
                load_tile64(db + 8192, A, (ch + 3) * 128 + 64, tid);
                CP_COMMIT();
            }

            const uint32_t ab = sb + S_ABUF + (ch & 3) * ACH_SZ;
#pragma unroll
            for (int sub = 0; sub < 2; sub++) {
                const uint32_t stb = ab + sub * 8192;
#pragma unroll
                for (int k16 = 0; k16 < 4; k16++) {
                    uint32_t ah[4];
                    uint32_t off = a_row_off + (uint32_t)(k16 * 32);
                    uint32_t sw = off ^ ((off >> 3) & 0x70);
                    ldmx4(ah, stb + sw);

                    const uint32_t kb = (uint32_t)(ch * 128 + sub * 64 + k16 * 16) * 2;
                    uint32_t b0[4], b1[4];
                    ldmx4(b0, wfrag + kb);
                    ldmx4(b1, wfrag + kb + 16);

#pragma unroll
                    for (int j = 0; j < 4; j++) mma16816(acc[j], ah, b0[j], b1[j]);
                }
            }
        }

        // ---- epilogue: fused gates, c in regs, write h fp16 ----
        __half* hout = g_h[par ^ 1];
#pragma unroll
        for (int rr = 0; rr < 2; rr++) {
            float2 fi0 = __half22float2(*(__half2*)&xq[rr].x);
            float2 go0 = __half22float2(*(__half2*)&xq[rr].y);
            float2 fi1 = __half22float2(*(__half2*)&xq[rr].z);
            float2 go1 = __half22float2(*(__half2*)&xq[rr].w);

            float hv[2];
            {
                const int q = rr * 2;
                float fg = sigf(acc[0][q] + fi0.x);
                float ig = sigf(acc[1][q] + fi0.y);
                float gg = tanhf(acc[2][q] + go0.x);
                float og = sigf(acc[3][q] + go0.y);
                float cn = gg * ig + creg[q] * fg;
                creg[q] = cn;
                hv[0] = tanhf(cn) * og;
            }
            {
                const int q = rr * 2 + 1;
                float fg = sigf(acc[0][q] + fi1.x);
                float ig = sigf(acc[1][q] + fi1.y);
                float gg = tanhf(acc[2][q] + go1.x);
                float og = sigf(acc[3][q] + go1.y);
                float cn = gg * ig + creg[q] * fg;
                creg[q] = cn;
                hv[1] = tanhf(cn) * og;
            }
            const int row = row0 + rr * 8;
            *(__half2*)(hout + (size_t)row * HH + u0) = __floats2half2_rn(hv[0], hv[1]);
        }

        // ---- prefetch next step's xq (independent of h; hides DRAM latency) ----
        if (t + 1 < TT) {
            const size_t toff = (size_t)(t + 1) * BB * N4;
            xq[0] = *(const uint4*)(xg_base0 + toff);
            xq[1] = *(const uint4*)(xg_base1 + toff);
        }

        // ---- per-group grid barrier (64 CTAs; elected-thread fence) ----
        if (t < TT - 1) {
            __syncthreads();          // all h-writes of this CTA done
            if (tid == 0) {
                __threadfence();      // gpu-scope visibility (elected thread)
                atomicAdd(barp, 1u);
                const unsigned target = 64u * (unsigned)(t + 1);
                unsigned v;
                do {
                    asm volatile("ld.global.acquire.gpu.b32 %0, [%1];"
                                 : "=r"(v) : "l"(barp));
                } while (v < target);
            }
            __syncthreads();
        }
    }
}

// ---------------------------------------------------------------------------
// Final projection
// ---------------------------------------------------------------------------
__global__ void proj_kernel(const float* __restrict__ Wph,
                            const float* __restrict__ bp,
                            float* __restrict__ out)
{
    const int b = blockIdx.x;
    const int w = threadIdx.x >> 5;
    const int lane = threadIdx.x & 31;
    const __half* hr = g_h[0] + (size_t)b * HH;

    float s = 0.0f;
    for (int h = lane; h < HH; h += 32)
        s += __half2float(hr[h]) * Wph[(size_t)h * CC + w];
#pragma unroll
    for (int off = 16; off; off >>= 1)
        s += __shfl_xor_sync(0xffffffffu, s, off);
    if (lane == 0)
        out[b * CC + w] = s + bp[w];
}

// ---------------------------------------------------------------------------
// Launch
// ---------------------------------------------------------------------------
extern "C" void kernel_launch(void* const* d_in, const int* in_sizes, int n_in,
                              void* d_out, int out_size)
{
    const float* x   = (const float*)d_in[0];
    const float* Wfx = (const float*)d_in[1];
    const float* Wix = (const float*)d_in[2];
    const float* Wgx = (const float*)d_in[3];
    const float* Wox = (const float*)d_in[4];
    const float* Wfh = (const float*)d_in[5];
    const float* Wih = (const float*)d_in[6];
    const float* Wgh = (const float*)d_in[7];
    const float* Woh = (const float*)d_in[8];
    const float* bf  = (const float*)d_in[9];
    const float* bi  = (const float*)d_in[10];
    const float* bg  = (const float*)d_in[11];
    const float* bo  = (const float*)d_in[12];
    const float* Wph = (const float*)d_in[13];
    const float* bp  = (const float*)d_in[14];
    float* out = (float*)d_out;

    cudaFuncSetAttribute(lstm_persist, cudaFuncAttributeMaxDynamicSharedMemorySize,
                         STEP_SMEM);
    cudaFuncSetAttribute(xg_mma, cudaFuncAttributeMaxDynamicSharedMemorySize,
                         XG_SMEM);

    // 1) weight pack (coalesced transpose; dst selected device-side), bias, h0
    dim3 gh(HH / 32, HH / 32);
    prep_pack<<<gh, 256>>>(Wfh, HH, 0, 0);
    prep_pack<<<gh, 256>>>(Wih, HH, 1, 0);
    prep_pack<<<gh, 256>>>(Wgh, HH, 2, 0);
    prep_pack<<<gh, 256>>>(Woh, HH, 3, 0);
    dim3 gx(DD / 32, HH / 32);
    prep_pack<<<gx, 256>>>(Wfx, DD, 0, 1);
    prep_pack<<<gx, 256>>>(Wix, DD, 1, 1);
    prep_pack<<<gx, 256>>>(Wgx, DD, 2, 1);
    prep_pack<<<gx, 256>>>(Wox, DD, 3, 1);
    prep_misc<<<(BB * HH + 255) / 256, 256>>>(bf, bi, bg, bo);

    // 2) x -> fp16
    prep_x<<<(TT * BB * DD / 4 + 255) / 256, 256>>>(x);

    // 3) input projections (fp16 MMA)
    xg_mma<<<dim3(N4 / 128, (TT * BB) / 128), 256, XG_SMEM>>>();

    // 4) persistent recurrence (fp16 MMA, 64x64 tiles, 128-wide chunks)
    lstm_persist<<<NCTA, NTHR, STEP_SMEM>>>();

    // 5) final projection
    proj_kernel<<<BB, CC * 32>>>(Wph, bp, out);
}